// round 10
// baseline (speedup 1.0000x reference)
#include <cuda_runtime.h>
#include <cuda_bf16.h>
#include <cstdint>

#define BB 2048
#define TT 2
#define NTOK 49
#define NHEAD 16
#define HDIM 32
#define CDIM 512
#define NN2 (NTOK*NTOK)

// ---------------- scratch (device globals; no allocs allowed) ----------------
__device__ unsigned short g_xh[(size_t)BB*NTOK*CDIM],    g_xl[(size_t)BB*NTOK*CDIM];
__device__ unsigned short g_mh[(size_t)BB*TT*NTOK*CDIM], g_ml[(size_t)BB*TT*NTOK*CDIM];
__device__ unsigned short g_oh[(size_t)BB*TT*NTOK*CDIM], g_ol[(size_t)BB*TT*NTOK*CDIM];
__device__ unsigned short g_qwh[CDIM*CDIM],    g_qwl[CDIM*CDIM];
__device__ unsigned short g_kvwh[2*CDIM*CDIM], g_kvwl[2*CDIM*CDIM];
__device__ unsigned short g_pwh[CDIM*CDIM],    g_pwl[CDIM*CDIM];
__device__ float g_q [(size_t)BB*NTOK*CDIM];
__device__ float g_kv[(size_t)BB*TT*NTOK*2*CDIM];
__device__ float g_bias[NHEAD*NN2];

// ---------------- PTX helpers (base-target only) ----------------
__device__ __forceinline__ uint32_t smem_u32(const void* p){
    uint32_t a;
    asm("{ .reg .u64 t; cvta.to.shared.u64 t, %1; cvt.u32.u64 %0, t; }":"=r"(a):"l"(p));
    return a;
}
#define CP16(d,s)   asm volatile("cp.async.cg.shared.global [%0], [%1], 16;"::"r"((uint32_t)(d)),"l"(s):"memory")
#define CP_COMMIT() asm volatile("cp.async.commit_group;":::"memory")
#define CP_WAIT1()  asm volatile("cp.async.wait_group 1;":::"memory")
#define CP_WAIT0()  asm volatile("cp.async.wait_group 0;":::"memory")

__device__ __forceinline__ void ldsm4(uint32_t* r, uint32_t addr){
    asm volatile("ldmatrix.sync.aligned.m8n8.x4.shared.b16 {%0,%1,%2,%3}, [%4];"
        : "=r"(r[0]),"=r"(r[1]),"=r"(r[2]),"=r"(r[3]) : "r"(addr));
}
__device__ __forceinline__ void mma16816(float* d, const uint32_t* a, const uint32_t* b){
    asm volatile("mma.sync.aligned.m16n8k16.row.col.f32.bf16.bf16.f32 "
        "{%0,%1,%2,%3}, {%4,%5,%6,%7}, {%8,%9}, {%0,%1,%2,%3};"
        : "+f"(d[0]),"+f"(d[1]),"+f"(d[2]),"+f"(d[3])
        : "r"(a[0]),"r"(a[1]),"r"(a[2]),"r"(a[3]), "r"(b[0]),"r"(b[1]));
}

// ---------------- fp32 -> bf16 hi/lo split ----------------
__global__ void split_kernel(const float* __restrict__ in,
                             unsigned short* __restrict__ hi,
                             unsigned short* __restrict__ lo, long long n4){
    long long i = (long long)blockIdx.x*256 + threadIdx.x;
    if (i >= n4) return;
    float4 v = reinterpret_cast<const float4*>(in)[i];
    float vs[4] = {v.x, v.y, v.z, v.w};
    unsigned short hb[4], lb[4];
#pragma unroll
    for (int c = 0; c < 4; c++){
        __nv_bfloat16 h = __float2bfloat16_rn(vs[c]);
        float r = vs[c] - __bfloat162float(h);
        hb[c] = __bfloat16_as_ushort(h);
        lb[c] = __bfloat16_as_ushort(__float2bfloat16_rn(r));
    }
    uint2 H, L;
    H.x = hb[0] | ((uint32_t)hb[1] << 16);  H.y = hb[2] | ((uint32_t)hb[3] << 16);
    L.x = lb[0] | ((uint32_t)lb[1] << 16);  L.y = lb[2] | ((uint32_t)lb[3] << 16);
    reinterpret_cast<uint2*>(hi)[i] = H;
    reinterpret_cast<uint2*>(lo)[i] = L;
}

// ---------------- bias gather ----------------
__global__ void bias_gather_kernel(const float* __restrict__ rpb,
                                   const int* __restrict__ rel){
    int g = blockIdx.x*256 + threadIdx.x;
    if (g >= NHEAD*NN2) return;
    int h = g / NN2, p = g - h*NN2;
    g_bias[g] = rpb[rel[p]*NHEAD + h];
}

// ---------------- warp-MMA GEMM: C = alpha*(A@W^T + bias) ----------------
// 3-term compensated bf16 (K'=1536 = AhWh|AlWh|AhWl). Tile 128x128, BK=64,
// 24 k-chunks (8 per phase), 8 warps (2M x 4N), warp tile 64x32 via m16n8k16,
// cp.async double buffer. smem rows padded to 144B (conflict-free ldmatrix).
#define RPITCH 72               // halves per padded smem row (144 bytes)
#define BUFB   (128*RPITCH*2)   // bytes per operand buffer = 18432
#define GEMM_SMEM (4*BUFB)      // 73728
#define NCHUNK 24

__global__ __launch_bounds__(256, 2)
void gemm_mma(const unsigned short* __restrict__ Ah, const unsigned short* __restrict__ Al,
              const unsigned short* __restrict__ Wh, const unsigned short* __restrict__ Wl,
              const float* __restrict__ bias, float* __restrict__ C, int N, float alpha){
    extern __shared__ __align__(16) unsigned char dyn[];
    const uint32_t base = smem_u32(dyn);
    const uint32_t abase[2] = {base,            base + BUFB};
    const uint32_t wbase[2] = {base + 2*BUFB,   base + 3*BUFB};

    const int tid = threadIdx.x, lane = tid & 31, wid = tid >> 5;
    const int wm = wid & 1, wn = wid >> 1;              // 2 x 4 warp grid
    const int m0 = blockIdx.y * 128, n0 = blockIdx.x * 128;

    const unsigned short* AP[3] = {Ah, Al, Ah};
    const unsigned short* WP[3] = {Wh, Wh, Wl};

    // chunk t (0..23): phase = t>>3, k0 = (t&7)*64 within the 512-K phase
    auto load_chunk = [&](int t, int b){
        const unsigned short* Ap = AP[t >> 3];
        const unsigned short* Wp = WP[t >> 3];
        const int k0 = (t & 7) * 64;
#pragma unroll
        for (int j = 0; j < 4; j++){
            int s = tid*4 + j;                           // 0..1023
            int r = s >> 3, c = s & 7;                   // 128 rows x 8 16B-chunks
            uint32_t off = (uint32_t)(r*144 + c*16);
            CP16(abase[b] + off, Ap + (size_t)(m0+r)*CDIM + k0 + c*8);
            CP16(wbase[b] + off, Wp + (size_t)(n0+r)*CDIM + k0 + c*8);
        }
        CP_COMMIT();
    };

    // lane offsets (bytes) within a buffer
    uint32_t a_off[4], b_off[2];
#pragma unroll
    for (int mt = 0; mt < 4; mt++)
        a_off[mt] = (uint32_t)((wm*64 + mt*16 + (lane & 15))*144 + ((lane >> 4) & 1)*16);
    {
        int g = lane >> 3;
#pragma unroll
        for (int q = 0; q < 2; q++)
            b_off[q] = (uint32_t)((wn*32 + (2*q + (g >> 1))*8 + (lane & 7))*144 + (g & 1)*16);
    }

    float acc[4][4][4];
#pragma unroll
    for (int i = 0; i < 4; i++)
#pragma unroll
        for (int j = 0; j < 4; j++)
#pragma unroll
            for (int k = 0; k < 4; k++) acc[i][j][k] = 0.f;

    load_chunk(0, 0);
    load_chunk(1, 1);

    for (int t = 0; t < NCHUNK; ++t){
        const int b = t & 1;
        if (t >= NCHUNK - 2) CP_WAIT0(); else CP_WAIT1();
        __syncthreads();

#pragma unroll
        for (int s = 0; s < 4; s++){                     // 4 x k16 within BK=64
            uint32_t af[4][4], bf[2][4];
#pragma unroll
            for (int mt = 0; mt < 4; mt++) ldsm4(af[mt], abase[b] + a_off[mt] + s*32);
#pragma unroll
            for (int q = 0; q < 2; q++)    ldsm4(bf[q],  wbase[b] + b_off[q] + s*32);
#pragma unroll
            for (int mt = 0; mt < 4; mt++){
                mma16816(acc[mt][0], af[mt], bf[0] + 0);
                mma16816(acc[mt][1], af[mt], bf[0] + 2);
                mma16816(acc[mt][2], af[mt], bf[1] + 0);
                mma16816(acc[mt][3], af[mt], bf[1] + 2);
            }
        }
        __syncthreads();
        if (t + 2 < NCHUNK) load_chunk(t + 2, b);
    }

    // epilogue
#pragma unroll
    for (int mt = 0; mt < 4; mt++){
#pragma unroll
        for (int nt = 0; nt < 4; nt++){
            int rg = m0 + wm*64 + mt*16 + (lane >> 2);
            int cg = n0 + wn*32 + nt*8 + 2*(lane & 3);
            float b0 = bias[cg], b1 = bias[cg + 1];
            float2 o0 = make_float2(alpha*(acc[mt][nt][0] + b0), alpha*(acc[mt][nt][1] + b1));
            float2 o1 = make_float2(alpha*(acc[mt][nt][2] + b0), alpha*(acc[mt][nt][3] + b1));
            *reinterpret_cast<float2*>(C + (size_t)rg*N + cg)       = o0;
            *reinterpret_cast<float2*>(C + (size_t)(rg + 8)*N + cg) = o1;
        }
    }
}

// ---------------- attention: 4x4 register-blocked, bf16-split output ----------
#define QP 36
#define SP 56

__global__ __launch_bounds__(128)
void attn_kernel(){
    const int bh = blockIdx.x;
    const int h  = bh & (NHEAD-1);
    const int bt = bh >> 4;
    const int b  = bt >> 1;
    __shared__ __align__(16) float sq[52*QP], sk[52*QP], sv[52*QP], sS[52*SP];
    const int tid = threadIdx.x;

    for (int p = tid; p < 52*HDIM; p += 128){
        int i = p >> 5, d = p & 31;
        float qv = 0.f, kv = 0.f, vv = 0.f;
        if (i < NTOK){
            qv = g_q[(size_t)(b*NTOK+i)*CDIM + h*HDIM + d];
            const float* kvr = g_kv + (size_t)(bt*NTOK+i)*(2*CDIM) + h*HDIM + d;
            kv = kvr[0];
            vv = kvr[CDIM];
        }
        sq[i*QP+d] = qv;
        sk[i*QP+d] = kv;
        sv[i*QP+d] = vv;
    }
    __syncthreads();

    const float* biasH = g_bias + h*NN2;
    for (int p = tid; p < 169; p += 128){
        int ti = p / 13, tj = p - ti*13;
        int i0 = ti*4, j0 = tj*4;
        float a[4][4] = {};
#pragma unroll
        for (int dd = 0; dd < 8; dd++){
            float4 qa[4], kb[4];
#pragma unroll
            for (int r = 0; r < 4; r++) qa[r] = *reinterpret_cast<const float4*>(&sq[(i0+r)*QP + dd*4]);
#pragma unroll
            for (int c = 0; c < 4; c++) kb[c] = *reinterpret_cast<const float4*>(&sk[(j0+c)*QP + dd*4]);
#pragma unroll
            for (int r = 0; r < 4; r++)
#pragma unroll
                for (int c = 0; c < 4; c++)
                    a[r][c] += qa[r].x*kb[c].x + qa[r].y*kb[c].y + qa[r].z*kb[c].z + qa[r].w*kb[c].w;
        }
#pragma unroll
        for (int r = 0; r < 4; r++)
#pragma unroll
            for (int c = 0; c < 4; c++){
                int i = i0 + r, j = j0 + c;
                float bv = (i < NTOK && j < NTOK) ? biasH[i*NTOK + j] : 0.f;
                sS[i*SP + j] = a[r][c] + bv;
            }
    }
    __syncthreads();

    const int warp = tid >> 5, lane = tid & 31;
    for (int i = warp; i < NTOK; i += 4){
        float* row = sS + i*SP;
        float x0 = row[lane];
        bool  v1 = (lane + 32) < NTOK;
        float x1 = v1 ? row[lane+32] : -3.402823466e38f;
        float m = fmaxf(x0, x1);
#pragma unroll
        for (int o = 16; o > 0; o >>= 1) m = fmaxf(m, __shfl_xor_sync(0xffffffffu, m, o));
        float e0 = __expf(x0 - m);
        float e1 = v1 ? __expf(x1 - m) : 0.f;
        float s = e0 + e1;
#pragma unroll
        for (int o = 16; o > 0; o >>= 1) s += __shfl_xor_sync(0xffffffffu, s, o);
        float inv = 1.0f / s;
        row[lane] = e0*inv;
        if (v1) row[lane+32] = e1*inv;
    }
    __syncthreads();

    for (int p = tid; p < 104; p += 128){
        int ti = p >> 3, td = p & 7;
        int i0 = ti*4, d0 = td*4;
        float a[4][4] = {};
        for (int m = 0; m < NTOK; m++){
            float4 vv = *reinterpret_cast<const float4*>(&sv[m*QP + d0]);
            float s0 = sS[(i0+0)*SP + m];
            float s1 = sS[(i0+1)*SP + m];
            float s2 = sS[(i0+2)*SP + m];
            float s3 = sS[(i0+3)*SP + m];
            a[0][0] += s0*vv.x; a[0][1] += s0*vv.y; a[0][2] += s0*vv.z; a[0][3] += s0*vv.w;
            a[1][0] += s1*vv.x; a[1][1] += s1*vv.y; a[1][2] += s1*vv.z; a[1][3] += s1*vv.w;
            a[2][0] += s2*vv.x; a[2][1] += s2*vv.y; a[2][2] += s2*vv.z; a[2][3] += s2*vv.w;
            a[3][0] += s3*vv.x; a[3][1] += s3*vv.y; a[3][2] += s3*vv.z; a[3][3] += s3*vv.w;
        }
#pragma unroll
        for (int r = 0; r < 4; r++){
            int i = i0 + r;
            if (i >= NTOK) break;
            size_t idx = (size_t)(bt*NTOK + i)*CDIM + h*HDIM + d0;
            unsigned short hb[4], lb[4];
#pragma unroll
            for (int c = 0; c < 4; c++){
                __nv_bfloat16 hh = __float2bfloat16_rn(a[r][c]);
                hb[c] = __bfloat16_as_ushort(hh);
                lb[c] = __bfloat16_as_ushort(__float2bfloat16_rn(a[r][c] - __bfloat162float(hh)));
            }
            uint2 H, L;
            H.x = hb[0] | ((uint32_t)hb[1] << 16);  H.y = hb[2] | ((uint32_t)hb[3] << 16);
            L.x = lb[0] | ((uint32_t)lb[1] << 16);  L.y = lb[2] | ((uint32_t)lb[3] << 16);
            *reinterpret_cast<uint2*>(&g_oh[idx]) = H;
            *reinterpret_cast<uint2*>(&g_ol[idx]) = L;
        }
    }
}

// ---------------- launch ----------------
extern "C" void kernel_launch(void* const* d_in, const int* in_sizes, int n_in,
                              void* d_out, int out_size){
    const float* x      = (const float*)d_in[0];
    const float* memory = (const float*)d_in[1];
    const float* rpb    = (const float*)d_in[2];
    const float* q_w    = (const float*)d_in[3];
    const float* q_b    = (const float*)d_in[4];
    const float* kv_w   = (const float*)d_in[5];
    const float* kv_b   = (const float*)d_in[6];
    const float* proj_w = (const float*)d_in[7];
    const float* proj_b = (const float*)d_in[8];
    const int*   rel    = (const int*)d_in[9];
    float* out = (float*)d_out;

    unsigned short *xh,*xl,*mh,*ml,*oh,*ol,*qwh,*qwl,*kvwh,*kvwl,*pwh,*pwl;
    float *pq,*pkv;
    cudaGetSymbolAddress((void**)&xh,g_xh);     cudaGetSymbolAddress((void**)&xl,g_xl);
    cudaGetSymbolAddress((void**)&mh,g_mh);     cudaGetSymbolAddress((void**)&ml,g_ml);
    cudaGetSymbolAddress((void**)&oh,g_oh);     cudaGetSymbolAddress((void**)&ol,g_ol);
    cudaGetSymbolAddress((void**)&qwh,g_qwh);   cudaGetSymbolAddress((void**)&qwl,g_qwl);
    cudaGetSymbolAddress((void**)&kvwh,g_kvwh); cudaGetSymbolAddress((void**)&kvwl,g_kvwl);
    cudaGetSymbolAddress((void**)&pwh,g_pwh);   cudaGetSymbolAddress((void**)&pwl,g_pwl);
    cudaGetSymbolAddress((void**)&pq,g_q);      cudaGetSymbolAddress((void**)&pkv,g_kv);

    cudaFuncSetAttribute(gemm_mma, cudaFuncAttributeMaxDynamicSharedMemorySize, GEMM_SMEM);

    const float scale = 0.17677669529663687f;  // 32^-0.5

    // launches 1-5: splits (so launch #6 = gemm_mma Q is the one ncu profiles)
    {
        long long n4x = (long long)BB*NTOK*CDIM/4;
        long long n4m = (long long)BB*TT*NTOK*CDIM/4;
        split_kernel<<<(unsigned)((n4x+255)/256),256>>>(x, xh, xl, n4x);
        split_kernel<<<(unsigned)((n4m+255)/256),256>>>(memory, mh, ml, n4m);
        split_kernel<<<(CDIM*CDIM/4+255)/256,256>>>(q_w, qwh, qwl, CDIM*CDIM/4);
        split_kernel<<<(2*CDIM*CDIM/4+255)/256,256>>>(kv_w, kvwh, kvwl, 2*CDIM*CDIM/4);
        split_kernel<<<(CDIM*CDIM/4+255)/256,256>>>(proj_w, pwh, pwl, CDIM*CDIM/4);
    }
    {   // #6: Q = scale*(x @ q_w^T + q_b)       M=100352 N=512
        dim3 g(CDIM/128, BB*NTOK/128);
        gemm_mma<<<g, 256, GEMM_SMEM>>>(xh, xl, qwh, qwl, q_b, pq, CDIM, scale);
    }
    {   // #7: KV = memory @ kv_w^T + kv_b      M=200704 N=1024
        dim3 g(2*CDIM/128, BB*TT*NTOK/128);
        gemm_mma<<<g, 256, GEMM_SMEM>>>(mh, ml, kvwh, kvwl, kv_b, pkv, 2*CDIM, 1.0f);
    }
    // #8: bias gather (must precede attn)
    bias_gather_kernel<<<(NHEAD*NN2 + 255)/256, 256>>>(rpb, rel);
    // #9: attention
    attn_kernel<<<BB*TT*NHEAD, 128>>>();
    {   // #10: out = attn @ proj_w^T + proj_b  M=200704 N=512
        dim3 g(CDIM/128, BB*TT*NTOK/128);
        gemm_mma<<<g, 256, GEMM_SMEM>>>(oh, ol, pwh, pwl, proj_b, out, CDIM, 1.0f);
    }
    (void)in_sizes; (void)n_in; (void)out_size;
}

// round 11
// speedup vs baseline: 1.0377x; 1.0377x over previous
#include <cuda_runtime.h>
#include <cuda_bf16.h>
#include <cstdint>

#define BB 2048
#define TT 2
#define NTOK 49
#define NHEAD 16
#define HDIM 32
#define CDIM 512
#define NN2 (NTOK*NTOK)

// ---------------- scratch (device globals; no allocs allowed) ----------------
__device__ unsigned short g_xh[(size_t)BB*NTOK*CDIM],    g_xl[(size_t)BB*NTOK*CDIM];
__device__ unsigned short g_mh[(size_t)BB*TT*NTOK*CDIM], g_ml[(size_t)BB*TT*NTOK*CDIM];
__device__ unsigned short g_oh[(size_t)BB*TT*NTOK*CDIM], g_ol[(size_t)BB*TT*NTOK*CDIM];
__device__ unsigned short g_qwh[CDIM*CDIM],    g_qwl[CDIM*CDIM];
__device__ unsigned short g_kvwh[2*CDIM*CDIM], g_kvwl[2*CDIM*CDIM];
__device__ unsigned short g_pwh[CDIM*CDIM],    g_pwl[CDIM*CDIM];
__device__ float g_q [(size_t)BB*NTOK*CDIM];
__device__ float g_kv[(size_t)BB*TT*NTOK*2*CDIM];
__device__ float g_bias[NHEAD*NN2];

// ---------------- PTX helpers (base-target only) ----------------
__device__ __forceinline__ uint32_t smem_u32(const void* p){
    uint32_t a;
    asm("{ .reg .u64 t; cvta.to.shared.u64 t, %1; cvt.u32.u64 %0, t; }":"=r"(a):"l"(p));
    return a;
}
#define CP16(d,s)   asm volatile("cp.async.cg.shared.global [%0], [%1], 16;"::"r"((uint32_t)(d)),"l"(s):"memory")
#define CP_COMMIT() asm volatile("cp.async.commit_group;":::"memory")
#define CP_WAIT2()  asm volatile("cp.async.wait_group 2;":::"memory")
#define CP_WAIT1()  asm volatile("cp.async.wait_group 1;":::"memory")
#define CP_WAIT0()  asm volatile("cp.async.wait_group 0;":::"memory")

__device__ __forceinline__ void ldsm4(uint32_t* r, uint32_t addr){
    asm volatile("ldmatrix.sync.aligned.m8n8.x4.shared.b16 {%0,%1,%2,%3}, [%4];"
        : "=r"(r[0]),"=r"(r[1]),"=r"(r[2]),"=r"(r[3]) : "r"(addr));
}
__device__ __forceinline__ void mma16816(float* d, const uint32_t* a, const uint32_t* b){
    asm volatile("mma.sync.aligned.m16n8k16.row.col.f32.bf16.bf16.f32 "
        "{%0,%1,%2,%3}, {%4,%5,%6,%7}, {%8,%9}, {%0,%1,%2,%3};"
        : "+f"(d[0]),"+f"(d[1]),"+f"(d[2]),"+f"(d[3])
        : "r"(a[0]),"r"(a[1]),"r"(a[2]),"r"(a[3]), "r"(b[0]),"r"(b[1]));
}

// ---------------- fp32 -> bf16 hi/lo split ----------------
__global__ void split_kernel(const float* __restrict__ in,
                             unsigned short* __restrict__ hi,
                             unsigned short* __restrict__ lo, long long n4){
    long long i = (long long)blockIdx.x*256 + threadIdx.x;
    if (i >= n4) return;
    float4 v = reinterpret_cast<const float4*>(in)[i];
    float vs[4] = {v.x, v.y, v.z, v.w};
    unsigned short hb[4], lb[4];
#pragma unroll
    for (int c = 0; c < 4; c++){
        __nv_bfloat16 h = __float2bfloat16_rn(vs[c]);
        float r = vs[c] - __bfloat162float(h);
        hb[c] = __bfloat16_as_ushort(h);
        lb[c] = __bfloat16_as_ushort(__float2bfloat16_rn(r));
    }
    uint2 H, L;
    H.x = hb[0] | ((uint32_t)hb[1] << 16);  H.y = hb[2] | ((uint32_t)hb[3] << 16);
    L.x = lb[0] | ((uint32_t)lb[1] << 16);  L.y = lb[2] | ((uint32_t)lb[3] << 16);
    reinterpret_cast<uint2*>(hi)[i] = H;
    reinterpret_cast<uint2*>(lo)[i] = L;
}

// ---------------- bias gather ----------------
__global__ void bias_gather_kernel(const float* __restrict__ rpb,
                                   const int* __restrict__ rel){
    int g = blockIdx.x*256 + threadIdx.x;
    if (g >= NHEAD*NN2) return;
    int h = g / NN2, p = g - h*NN2;
    g_bias[g] = rpb[rel[p]*NHEAD + h];
}

// ---------------- warp-MMA GEMM: C = alpha*(A@W^T + bias) ----------------
// 3-term compensated bf16 (K'=1536 = AhWh|AlWh|AhWl). Tile 128x128, BK=32,
// 48 k-chunks (16 per phase), 8 warps (2M x 4N), warp tile 64x32 via m16n8k16.
// 3-stage cp.async pipeline (wait_group 2 -> ~2 chunk-times of load latency
// budget). smem rows 80B (conflict-free ldmatrix). Proven R8 offsets.
#define ABUF  (128*40*2)        // 10240 bytes per operand buffer
#define GEMM_SMEM (6*ABUF)      // 61440 (3 stages x {A,W})
#define NCHUNK 48

__global__ __launch_bounds__(256, 2)
void gemm_mma(const unsigned short* __restrict__ Ah, const unsigned short* __restrict__ Al,
              const unsigned short* __restrict__ Wh, const unsigned short* __restrict__ Wl,
              const float* __restrict__ bias, float* __restrict__ C, int N, float alpha){
    extern __shared__ __align__(16) unsigned char dyn[];
    const uint32_t base = smem_u32(dyn);
    const uint32_t abase[3] = {base,          base + ABUF,   base + 2*ABUF};
    const uint32_t wbase[3] = {base + 3*ABUF, base + 4*ABUF, base + 5*ABUF};

    const int tid = threadIdx.x, lane = tid & 31, wid = tid >> 5;
    const int wm = wid & 1, wn = wid >> 1;              // 2 x 4 warp grid
    const int m0 = blockIdx.y * 128, n0 = blockIdx.x * 128;

    const unsigned short* AP[3] = {Ah, Al, Ah};
    const unsigned short* WP[3] = {Wh, Wh, Wl};

    // chunk t (0..47): phase = t>>4, k0 = (t&15)*32 within the 512-K phase
    auto load_chunk = [&](int t, int b){
        const unsigned short* Ap = AP[t >> 4];
        const unsigned short* Wp = WP[t >> 4];
        const int k0 = (t & 15) * 32;
#pragma unroll
        for (int j = 0; j < 2; j++){
            int s = tid*2 + j;                           // 0..511
            int r = s >> 2, c = s & 3;                   // 128 rows x 4 16B-chunks
            uint32_t off = (uint32_t)(r*80 + c*16);
            CP16(abase[b] + off, Ap + (size_t)(m0+r)*CDIM + k0 + c*8);
            CP16(wbase[b] + off, Wp + (size_t)(n0+r)*CDIM + k0 + c*8);
        }
        CP_COMMIT();
    };

    // lane offsets (bytes) within a buffer (R8-proven, 80B pitch)
    uint32_t a_off[4], b_off[2];
#pragma unroll
    for (int mt = 0; mt < 4; mt++)
        a_off[mt] = (uint32_t)((wm*64 + mt*16 + (lane & 15))*80 + ((lane >> 4) & 1)*16);
    {
        int g = lane >> 3;
#pragma unroll
        for (int q = 0; q < 2; q++)
            b_off[q] = (uint32_t)((wn*32 + (2*q + (g >> 1))*8 + (lane & 7))*80 + (g & 1)*16);
    }

    float acc[4][4][4];
#pragma unroll
    for (int i = 0; i < 4; i++)
#pragma unroll
        for (int j = 0; j < 4; j++)
#pragma unroll
            for (int k = 0; k < 4; k++) acc[i][j][k] = 0.f;

    load_chunk(0, 0);
    load_chunk(1, 1);
    load_chunk(2, 2);

    int b = 0;
    for (int t = 0; t < NCHUNK; ++t){
        if (t <= NCHUNK - 3)      CP_WAIT2();
        else if (t == NCHUNK - 2) CP_WAIT1();
        else                      CP_WAIT0();
        __syncthreads();

#pragma unroll
        for (int s = 0; s < 2; s++){                     // 2 x k16 within BK=32
            uint32_t af[4][4], bf[2][4];
#pragma unroll
            for (int mt = 0; mt < 4; mt++) ldsm4(af[mt], abase[b] + a_off[mt] + s*32);
#pragma unroll
            for (int q = 0; q < 2; q++)    ldsm4(bf[q],  wbase[b] + b_off[q] + s*32);
#pragma unroll
            for (int mt = 0; mt < 4; mt++){
                mma16816(acc[mt][0], af[mt], bf[0] + 0);
                mma16816(acc[mt][1], af[mt], bf[0] + 2);
                mma16816(acc[mt][2], af[mt], bf[1] + 0);
                mma16816(acc[mt][3], af[mt], bf[1] + 2);
            }
        }
        __syncthreads();
        if (t + 3 < NCHUNK) load_chunk(t + 3, b);
        b = (b == 2) ? 0 : b + 1;
    }

    // epilogue
#pragma unroll
    for (int mt = 0; mt < 4; mt++){
#pragma unroll
        for (int nt = 0; nt < 4; nt++){
            int rg = m0 + wm*64 + mt*16 + (lane >> 2);
            int cg = n0 + wn*32 + nt*8 + 2*(lane & 3);
            float b0 = bias[cg], b1 = bias[cg + 1];
            float2 o0 = make_float2(alpha*(acc[mt][nt][0] + b0), alpha*(acc[mt][nt][1] + b1));
            float2 o1 = make_float2(alpha*(acc[mt][nt][2] + b0), alpha*(acc[mt][nt][3] + b1));
            *reinterpret_cast<float2*>(C + (size_t)rg*N + cg)       = o0;
            *reinterpret_cast<float2*>(C + (size_t)(rg + 8)*N + cg) = o1;
        }
    }
}

// ---------------- attention: 4x4 register-blocked, bf16-split output ----------
#define QP 36
#define SP 56

__global__ __launch_bounds__(128)
void attn_kernel(){
    const int bh = blockIdx.x;
    const int h  = bh & (NHEAD-1);
    const int bt = bh >> 4;
    const int b  = bt >> 1;
    __shared__ __align__(16) float sq[52*QP], sk[52*QP], sv[52*QP], sS[52*SP];
    const int tid = threadIdx.x;

    for (int p = tid; p < 52*HDIM; p += 128){
        int i = p >> 5, d = p & 31;
        float qv = 0.f, kv = 0.f, vv = 0.f;
        if (i < NTOK){
            qv = g_q[(size_t)(b*NTOK+i)*CDIM + h*HDIM + d];
            const float* kvr = g_kv + (size_t)(bt*NTOK+i)*(2*CDIM) + h*HDIM + d;
            kv = kvr[0];
            vv = kvr[CDIM];
        }
        sq[i*QP+d] = qv;
        sk[i*QP+d] = kv;
        sv[i*QP+d] = vv;
    }
    __syncthreads();

    const float* biasH = g_bias + h*NN2;
    for (int p = tid; p < 169; p += 128){
        int ti = p / 13, tj = p - ti*13;
        int i0 = ti*4, j0 = tj*4;
        float a[4][4] = {};
#pragma unroll
        for (int dd = 0; dd < 8; dd++){
            float4 qa[4], kb[4];
#pragma unroll
            for (int r = 0; r < 4; r++) qa[r] = *reinterpret_cast<const float4*>(&sq[(i0+r)*QP + dd*4]);
#pragma unroll
            for (int c = 0; c < 4; c++) kb[c] = *reinterpret_cast<const float4*>(&sk[(j0+c)*QP + dd*4]);
#pragma unroll
            for (int r = 0; r < 4; r++)
#pragma unroll
                for (int c = 0; c < 4; c++)
                    a[r][c] += qa[r].x*kb[c].x + qa[r].y*kb[c].y + qa[r].z*kb[c].z + qa[r].w*kb[c].w;
        }
#pragma unroll
        for (int r = 0; r < 4; r++)
#pragma unroll
            for (int c = 0; c < 4; c++){
                int i = i0 + r, j = j0 + c;
                float bv = (i < NTOK && j < NTOK) ? biasH[i*NTOK + j] : 0.f;
                sS[i*SP + j] = a[r][c] + bv;
            }
    }
    __syncthreads();

    const int warp = tid >> 5, lane = tid & 31;
    for (int i = warp; i < NTOK; i += 4){
        float* row = sS + i*SP;
        float x0 = row[lane];
        bool  v1 = (lane + 32) < NTOK;
        float x1 = v1 ? row[lane+32] : -3.402823466e38f;
        float m = fmaxf(x0, x1);
#pragma unroll
        for (int o = 16; o > 0; o >>= 1) m = fmaxf(m, __shfl_xor_sync(0xffffffffu, m, o));
        float e0 = __expf(x0 - m);
        float e1 = v1 ? __expf(x1 - m) : 0.f;
        float s = e0 + e1;
#pragma unroll
        for (int o = 16; o > 0; o >>= 1) s += __shfl_xor_sync(0xffffffffu, s, o);
        float inv = 1.0f / s;
        row[lane] = e0*inv;
        if (v1) row[lane+32] = e1*inv;
    }
    __syncthreads();

    for (int p = tid; p < 104; p += 128){
        int ti = p >> 3, td = p & 7;
        int i0 = ti*4, d0 = td*4;
        float a[4][4] = {};
        for (int m = 0; m < NTOK; m++){
            float4 vv = *reinterpret_cast<const float4*>(&sv[m*QP + d0]);
            float s0 = sS[(i0+0)*SP + m];
            float s1 = sS[(i0+1)*SP + m];
            float s2 = sS[(i0+2)*SP + m];
            float s3 = sS[(i0+3)*SP + m];
            a[0][0] += s0*vv.x; a[0][1] += s0*vv.y; a[0][2] += s0*vv.z; a[0][3] += s0*vv.w;
            a[1][0] += s1*vv.x; a[1][1] += s1*vv.y; a[1][2] += s1*vv.z; a[1][3] += s1*vv.w;
            a[2][0] += s2*vv.x; a[2][1] += s2*vv.y; a[2][2] += s2*vv.z; a[2][3] += s2*vv.w;
            a[3][0] += s3*vv.x; a[3][1] += s3*vv.y; a[3][2] += s3*vv.z; a[3][3] += s3*vv.w;
        }
#pragma unroll
        for (int r = 0; r < 4; r++){
            int i = i0 + r;
            if (i >= NTOK) break;
            size_t idx = (size_t)(bt*NTOK + i)*CDIM + h*HDIM + d0;
            unsigned short hb[4], lb[4];
#pragma unroll
            for (int c = 0; c < 4; c++){
                __nv_bfloat16 hh = __float2bfloat16_rn(a[r][c]);
                hb[c] = __bfloat16_as_ushort(hh);
                lb[c] = __bfloat16_as_ushort(__float2bfloat16_rn(a[r][c] - __bfloat162float(hh)));
            }
            uint2 H, L;
            H.x = hb[0] | ((uint32_t)hb[1] << 16);  H.y = hb[2] | ((uint32_t)hb[3] << 16);
            L.x = lb[0] | ((uint32_t)lb[1] << 16);  L.y = lb[2] | ((uint32_t)lb[3] << 16);
            *reinterpret_cast<uint2*>(&g_oh[idx]) = H;
            *reinterpret_cast<uint2*>(&g_ol[idx]) = L;
        }
    }
}

// ---------------- launch ----------------
extern "C" void kernel_launch(void* const* d_in, const int* in_sizes, int n_in,
                              void* d_out, int out_size){
    const float* x      = (const float*)d_in[0];
    const float* memory = (const float*)d_in[1];
    const float* rpb    = (const float*)d_in[2];
    const float* q_w    = (const float*)d_in[3];
    const float* q_b    = (const float*)d_in[4];
    const float* kv_w   = (const float*)d_in[5];
    const float* kv_b   = (const float*)d_in[6];
    const float* proj_w = (const float*)d_in[7];
    const float* proj_b = (const float*)d_in[8];
    const int*   rel    = (const int*)d_in[9];
    float* out = (float*)d_out;

    unsigned short *xh,*xl,*mh,*ml,*oh,*ol,*qwh,*qwl,*kvwh,*kvwl,*pwh,*pwl;
    float *pq,*pkv;
    cudaGetSymbolAddress((void**)&xh,g_xh);     cudaGetSymbolAddress((void**)&xl,g_xl);
    cudaGetSymbolAddress((void**)&mh,g_mh);     cudaGetSymbolAddress((void**)&ml,g_ml);
    cudaGetSymbolAddress((void**)&oh,g_oh);     cudaGetSymbolAddress((void**)&ol,g_ol);
    cudaGetSymbolAddress((void**)&qwh,g_qwh);   cudaGetSymbolAddress((void**)&qwl,g_qwl);
    cudaGetSymbolAddress((void**)&kvwh,g_kvwh); cudaGetSymbolAddress((void**)&kvwl,g_kvwl);
    cudaGetSymbolAddress((void**)&pwh,g_pwh);   cudaGetSymbolAddress((void**)&pwl,g_pwl);
    cudaGetSymbolAddress((void**)&pq,g_q);      cudaGetSymbolAddress((void**)&pkv,g_kv);

    cudaFuncSetAttribute(gemm_mma, cudaFuncAttributeMaxDynamicSharedMemorySize, GEMM_SMEM);

    const float scale = 0.17677669529663687f;  // 32^-0.5
    long long n4x = (long long)BB*NTOK*CDIM/4;
    long long n4m = (long long)BB*TT*NTOK*CDIM/4;

    // Launch order chosen so the ncu window (observed: our launch #4) hits
    // gemm_mma(KV) — the dominant kernel. Dependencies preserved.
    split_kernel<<<(unsigned)((n4m+255)/256),256>>>(memory, mh, ml, n4m);        // #1
    split_kernel<<<(2*CDIM*CDIM/4+255)/256,256>>>(kv_w, kvwh, kvwl, 2*CDIM*CDIM/4); // #2
    split_kernel<<<(unsigned)((n4x+255)/256),256>>>(x, xh, xl, n4x);             // #3
    {   // #4 (PROFILED): KV = memory @ kv_w^T + kv_b   M=200704 N=1024
        dim3 g(2*CDIM/128, BB*TT*NTOK/128);
        gemm_mma<<<g, 256, GEMM_SMEM>>>(mh, ml, kvwh, kvwl, kv_b, pkv, 2*CDIM, 1.0f);
    }
    split_kernel<<<(CDIM*CDIM/4+255)/256,256>>>(q_w, qwh, qwl, CDIM*CDIM/4);     // #5
    {   // #6: Q = scale*(x @ q_w^T + q_b)              M=100352 N=512
        dim3 g(CDIM/128, BB*NTOK/128);
        gemm_mma<<<g, 256, GEMM_SMEM>>>(xh, xl, qwh, qwl, q_b, pq, CDIM, scale);
    }
    split_kernel<<<(CDIM*CDIM/4+255)/256,256>>>(proj_w, pwh, pwl, CDIM*CDIM/4);  // #7
    bias_gather_kernel<<<(NHEAD*NN2 + 255)/256, 256>>>(rpb, rel);                // #8
    attn_kernel<<<BB*TT*NHEAD, 128>>>();                                         // #9
    {   // #10: out = attn @ proj_w^T + proj_b          M=200704 N=512
        dim3 g(CDIM/128, BB*TT*NTOK/128);
        gemm_mma<<<g, 256, GEMM_SMEM>>>(oh, ol, pwh, pwl, proj_b, out, CDIM, 1.0f);
    }
    (void)in_sizes; (void)n_in; (void)out_size;
}

// round 12
// speedup vs baseline: 1.1004x; 1.0604x over previous
#include <cuda_runtime.h>
#include <cuda_bf16.h>
#include <cstdint>

#define BB 2048
#define TT 2
#define NTOK 49
#define NHEAD 16
#define HDIM 32
#define CDIM 512
#define NN2 (NTOK*NTOK)

// ---------------- scratch (device globals; no allocs allowed) ----------------
__device__ unsigned short g_xh[(size_t)BB*NTOK*CDIM],    g_xl[(size_t)BB*NTOK*CDIM];
__device__ unsigned short g_mh[(size_t)BB*TT*NTOK*CDIM], g_ml[(size_t)BB*TT*NTOK*CDIM];
__device__ unsigned short g_oh[(size_t)BB*TT*NTOK*CDIM], g_ol[(size_t)BB*TT*NTOK*CDIM];
__device__ unsigned short g_qwh[CDIM*CDIM],    g_qwl[CDIM*CDIM];
__device__ unsigned short g_kvwh[2*CDIM*CDIM], g_kvwl[2*CDIM*CDIM];
__device__ unsigned short g_pwh[CDIM*CDIM],    g_pwl[CDIM*CDIM];
__device__ float g_q [(size_t)BB*NTOK*CDIM];
__device__ float g_kv[(size_t)BB*TT*NTOK*2*CDIM];
__device__ float g_bias[NHEAD*NN2];

// ---------------- PTX helpers (base-target only) ----------------
__device__ __forceinline__ uint32_t smem_u32(const void* p){
    uint32_t a;
    asm("{ .reg .u64 t; cvta.to.shared.u64 t, %1; cvt.u32.u64 %0, t; }":"=r"(a):"l"(p));
    return a;
}
#define CP16(d,s)   asm volatile("cp.async.cg.shared.global [%0], [%1], 16;"::"r"((uint32_t)(d)),"l"(s):"memory")
#define CP_COMMIT() asm volatile("cp.async.commit_group;":::"memory")
#define CP_WAIT2()  asm volatile("cp.async.wait_group 2;":::"memory")
#define CP_WAIT1()  asm volatile("cp.async.wait_group 1;":::"memory")
#define CP_WAIT0()  asm volatile("cp.async.wait_group 0;":::"memory")

__device__ __forceinline__ void ldsm4(uint32_t* r, uint32_t addr){
    asm volatile("ldmatrix.sync.aligned.m8n8.x4.shared.b16 {%0,%1,%2,%3}, [%4];"
        : "=r"(r[0]),"=r"(r[1]),"=r"(r[2]),"=r"(r[3]) : "r"(addr));
}
__device__ __forceinline__ void mma16816(float* d, const uint32_t* a, const uint32_t* b){
    asm volatile("mma.sync.aligned.m16n8k16.row.col.f32.bf16.bf16.f32 "
        "{%0,%1,%2,%3}, {%4,%5,%6,%7}, {%8,%9}, {%0,%1,%2,%3};"
        : "+f"(d[0]),"+f"(d[1]),"+f"(d[2]),"+f"(d[3])
        : "r"(a[0]),"r"(a[1]),"r"(a[2]),"r"(a[3]), "r"(b[0]),"r"(b[1]));
}

// ---------------- fp32 -> bf16 hi/lo split ----------------
__global__ void split_kernel(const float* __restrict__ in,
                             unsigned short* __restrict__ hi,
                             unsigned short* __restrict__ lo, long long n4){
    long long i = (long long)blockIdx.x*256 + threadIdx.x;
    if (i >= n4) return;
    float4 v = reinterpret_cast<const float4*>(in)[i];
    float vs[4] = {v.x, v.y, v.z, v.w};
    unsigned short hb[4], lb[4];
#pragma unroll
    for (int c = 0; c < 4; c++){
        __nv_bfloat16 h = __float2bfloat16_rn(vs[c]);
        float r = vs[c] - __bfloat162float(h);
        hb[c] = __bfloat16_as_ushort(h);
        lb[c] = __bfloat16_as_ushort(__float2bfloat16_rn(r));
    }
    uint2 H, L;
    H.x = hb[0] | ((uint32_t)hb[1] << 16);  H.y = hb[2] | ((uint32_t)hb[3] << 16);
    L.x = lb[0] | ((uint32_t)lb[1] << 16);  L.y = lb[2] | ((uint32_t)lb[3] << 16);
    reinterpret_cast<uint2*>(hi)[i] = H;
    reinterpret_cast<uint2*>(lo)[i] = L;
}

// ---------------- bias gather ----------------
__global__ void bias_gather_kernel(const float* __restrict__ rpb,
                                   const int* __restrict__ rel){
    int g = blockIdx.x*256 + threadIdx.x;
    if (g >= NHEAD*NN2) return;
    int h = g / NN2, p = g - h*NN2;
    g_bias[g] = rpb[rel[p]*NHEAD + h];
}

// ---------------- warp-MMA GEMM: C = alpha*(A@W^T + bias) ----------------
// 3-term compensated bf16 (K'=1536 = AhWh|AlWh|AhWl). Tile 128x128, BK=32,
// 48 k-chunks, 8 warps (2M x 4N), warp tile 64x32 via m16n8k16.
// 4-stage cp.async pipeline, ONE __syncthreads per iteration (CUTLASS
// multistage pattern: refilled buffer (t+3)%4 was last read at iter t-1,
// ordered by the top-of-iter barrier). 80B smem pitch (conflict-free ldmatrix).
#define ABUF  (128*40*2)        // 10240 bytes per operand buffer
#define NSTAGE 4
#define GEMM_SMEM (2*NSTAGE*ABUF)   // 81920
#define NCHUNK 48

__global__ __launch_bounds__(256, 2)
void gemm_mma(const unsigned short* __restrict__ Ah, const unsigned short* __restrict__ Al,
              const unsigned short* __restrict__ Wh, const unsigned short* __restrict__ Wl,
              const float* __restrict__ bias, float* __restrict__ C, int N, float alpha){
    extern __shared__ __align__(16) unsigned char dyn[];
    const uint32_t base = smem_u32(dyn);
    uint32_t abase[NSTAGE], wbase[NSTAGE];
#pragma unroll
    for (int i = 0; i < NSTAGE; i++){
        abase[i] = base + i*ABUF;
        wbase[i] = base + (NSTAGE + i)*ABUF;
    }

    const int tid = threadIdx.x, lane = tid & 31, wid = tid >> 5;
    const int wm = wid & 1, wn = wid >> 1;              // 2 x 4 warp grid
    const int m0 = blockIdx.y * 128, n0 = blockIdx.x * 128;

    const unsigned short* AP[3] = {Ah, Al, Ah};
    const unsigned short* WP[3] = {Wh, Wh, Wl};

    // chunk t (0..47): phase = t>>4, k0 = (t&15)*32 within the 512-K phase
    auto load_chunk = [&](int t, int b){
        const unsigned short* Ap = AP[t >> 4];
        const unsigned short* Wp = WP[t >> 4];
        const int k0 = (t & 15) * 32;
#pragma unroll
        for (int j = 0; j < 2; j++){
            int s = tid*2 + j;                           // 0..511
            int r = s >> 2, c = s & 3;                   // 128 rows x 4 16B-chunks
            uint32_t off = (uint32_t)(r*80 + c*16);
            CP16(abase[b] + off, Ap + (size_t)(m0+r)*CDIM + k0 + c*8);
            CP16(wbase[b] + off, Wp + (size_t)(n0+r)*CDIM + k0 + c*8);
        }
        CP_COMMIT();
    };

    // lane offsets (bytes) within a buffer (R8-proven, 80B pitch)
    uint32_t a_off[4], b_off[2];
#pragma unroll
    for (int mt = 0; mt < 4; mt++)
        a_off[mt] = (uint32_t)((wm*64 + mt*16 + (lane & 15))*80 + ((lane >> 4) & 1)*16);
    {
        int g = lane >> 3;
#pragma unroll
        for (int q = 0; q < 2; q++)
            b_off[q] = (uint32_t)((wn*32 + (2*q + (g >> 1))*8 + (lane & 7))*80 + (g & 1)*16);
    }

    float acc[4][4][4];
#pragma unroll
    for (int i = 0; i < 4; i++)
#pragma unroll
        for (int j = 0; j < 4; j++)
#pragma unroll
            for (int k = 0; k < 4; k++) acc[i][j][k] = 0.f;

    load_chunk(0, 0);
    load_chunk(1, 1);
    load_chunk(2, 2);

    for (int t = 0; t < NCHUNK; ++t){
        const int b = t & (NSTAGE - 1);
        // guarantee chunk t's group is complete (tail: fewer groups in flight)
        if (t < NCHUNK - 2)       CP_WAIT2();
        else if (t == NCHUNK - 2) CP_WAIT1();
        else                      CP_WAIT0();
        __syncthreads();                                 // ONE barrier per iter

#pragma unroll
        for (int s = 0; s < 2; s++){                     // 2 x k16 within BK=32
            uint32_t af[4][4], bf[2][4];
#pragma unroll
            for (int mt = 0; mt < 4; mt++) ldsm4(af[mt], abase[b] + a_off[mt] + s*32);
#pragma unroll
            for (int q = 0; q < 2; q++)    ldsm4(bf[q],  wbase[b] + b_off[q] + s*32);
#pragma unroll
            for (int mt = 0; mt < 4; mt++){
                mma16816(acc[mt][0], af[mt], bf[0] + 0);
                mma16816(acc[mt][1], af[mt], bf[0] + 2);
                mma16816(acc[mt][2], af[mt], bf[1] + 0);
                mma16816(acc[mt][3], af[mt], bf[1] + 2);
            }
        }
        // refill buffer (t+3)%4 — last read at iter t-1, ordered by the
        // __syncthreads above; no second barrier needed.
        if (t + 3 < NCHUNK) load_chunk(t + 3, (t + 3) & (NSTAGE - 1));
    }

    // epilogue
#pragma unroll
    for (int mt = 0; mt < 4; mt++){
#pragma unroll
        for (int nt = 0; nt < 4; nt++){
            int rg = m0 + wm*64 + mt*16 + (lane >> 2);
            int cg = n0 + wn*32 + nt*8 + 2*(lane & 3);
            float b0 = bias[cg], b1 = bias[cg + 1];
            float2 o0 = make_float2(alpha*(acc[mt][nt][0] + b0), alpha*(acc[mt][nt][1] + b1));
            float2 o1 = make_float2(alpha*(acc[mt][nt][2] + b0), alpha*(acc[mt][nt][3] + b1));
            *reinterpret_cast<float2*>(C + (size_t)rg*N + cg)       = o0;
            *reinterpret_cast<float2*>(C + (size_t)(rg + 8)*N + cg) = o1;
        }
    }
}

// ---------------- attention: 4x4 register-blocked, bf16-split output ----------
#define QP 36
#define SP 56

__global__ __launch_bounds__(128)
void attn_kernel(){
    const int bh = blockIdx.x;
    const int h  = bh & (NHEAD-1);
    const int bt = bh >> 4;
    const int b  = bt >> 1;
    __shared__ __align__(16) float sq[52*QP], sk[52*QP], sv[52*QP], sS[52*SP];
    const int tid = threadIdx.x;

    for (int p = tid; p < 52*HDIM; p += 128){
        int i = p >> 5, d = p & 31;
        float qv = 0.f, kv = 0.f, vv = 0.f;
        if (i < NTOK){
            qv = g_q[(size_t)(b*NTOK+i)*CDIM + h*HDIM + d];
            const float* kvr = g_kv + (size_t)(bt*NTOK+i)*(2*CDIM) + h*HDIM + d;
            kv = kvr[0];
            vv = kvr[CDIM];
        }
        sq[i*QP+d] = qv;
        sk[i*QP+d] = kv;
        sv[i*QP+d] = vv;
    }
    __syncthreads();

    const float* biasH = g_bias + h*NN2;
    for (int p = tid; p < 169; p += 128){
        int ti = p / 13, tj = p - ti*13;
        int i0 = ti*4, j0 = tj*4;
        float a[4][4] = {};
#pragma unroll
        for (int dd = 0; dd < 8; dd++){
            float4 qa[4], kb[4];
#pragma unroll
            for (int r = 0; r < 4; r++) qa[r] = *reinterpret_cast<const float4*>(&sq[(i0+r)*QP + dd*4]);
#pragma unroll
            for (int c = 0; c < 4; c++) kb[c] = *reinterpret_cast<const float4*>(&sk[(j0+c)*QP + dd*4]);
#pragma unroll
            for (int r = 0; r < 4; r++)
#pragma unroll
                for (int c = 0; c < 4; c++)
                    a[r][c] += qa[r].x*kb[c].x + qa[r].y*kb[c].y + qa[r].z*kb[c].z + qa[r].w*kb[c].w;
        }
#pragma unroll
        for (int r = 0; r < 4; r++)
#pragma unroll
            for (int c = 0; c < 4; c++){
                int i = i0 + r, j = j0 + c;
                float bv = (i < NTOK && j < NTOK) ? biasH[i*NTOK + j] : 0.f;
                sS[i*SP + j] = a[r][c] + bv;
            }
    }
    __syncthreads();

    const int warp = tid >> 5, lane = tid & 31;
    for (int i = warp; i < NTOK; i += 4){
        float* row = sS + i*SP;
        float x0 = row[lane];
        bool  v1 = (lane + 32) < NTOK;
        float x1 = v1 ? row[lane+32] : -3.402823466e38f;
        float m = fmaxf(x0, x1);
#pragma unroll
        for (int o = 16; o > 0; o >>= 1) m = fmaxf(m, __shfl_xor_sync(0xffffffffu, m, o));
        float e0 = __expf(x0 - m);
        float e1 = v1 ? __expf(x1 - m) : 0.f;
        float s = e0 + e1;
#pragma unroll
        for (int o = 16; o > 0; o >>= 1) s += __shfl_xor_sync(0xffffffffu, s, o);
        float inv = 1.0f / s;
        row[lane] = e0*inv;
        if (v1) row[lane+32] = e1*inv;
    }
    __syncthreads();

    for (int p = tid; p < 104; p += 128){
        int ti = p >> 3, td = p & 7;
        int i0 = ti*4, d0 = td*4;
        float a[4][4] = {};
        for (int m = 0; m < NTOK; m++){
            float4 vv = *reinterpret_cast<const float4*>(&sv[m*QP + d0]);
            float s0 = sS[(i0+0)*SP + m];
            float s1 = sS[(i0+1)*SP + m];
            float s2 = sS[(i0+2)*SP + m];
            float s3 = sS[(i0+3)*SP + m];
            a[0][0] += s0*vv.x; a[0][1] += s0*vv.y; a[0][2] += s0*vv.z; a[0][3] += s0*vv.w;
            a[1][0] += s1*vv.x; a[1][1] += s1*vv.y; a[1][2] += s1*vv.z; a[1][3] += s1*vv.w;
            a[2][0] += s2*vv.x; a[2][1] += s2*vv.y; a[2][2] += s2*vv.z; a[2][3] += s2*vv.w;
            a[3][0] += s3*vv.x; a[3][1] += s3*vv.y; a[3][2] += s3*vv.z; a[3][3] += s3*vv.w;
        }
#pragma unroll
        for (int r = 0; r < 4; r++){
            int i = i0 + r;
            if (i >= NTOK) break;
            size_t idx = (size_t)(bt*NTOK + i)*CDIM + h*HDIM + d0;
            unsigned short hb[4], lb[4];
#pragma unroll
            for (int c = 0; c < 4; c++){
                __nv_bfloat16 hh = __float2bfloat16_rn(a[r][c]);
                hb[c] = __bfloat16_as_ushort(hh);
                lb[c] = __bfloat16_as_ushort(__float2bfloat16_rn(a[r][c] - __bfloat162float(hh)));
            }
            uint2 H, L;
            H.x = hb[0] | ((uint32_t)hb[1] << 16);  H.y = hb[2] | ((uint32_t)hb[3] << 16);
            L.x = lb[0] | ((uint32_t)lb[1] << 16);  L.y = lb[2] | ((uint32_t)lb[3] << 16);
            *reinterpret_cast<uint2*>(&g_oh[idx]) = H;
            *reinterpret_cast<uint2*>(&g_ol[idx]) = L;
        }
    }
}

// ---------------- launch ----------------
extern "C" void kernel_launch(void* const* d_in, const int* in_sizes, int n_in,
                              void* d_out, int out_size){
    const float* x      = (const float*)d_in[0];
    const float* memory = (const float*)d_in[1];
    const float* rpb    = (const float*)d_in[2];
    const float* q_w    = (const float*)d_in[3];
    const float* q_b    = (const float*)d_in[4];
    const float* kv_w   = (const float*)d_in[5];
    const float* kv_b   = (const float*)d_in[6];
    const float* proj_w = (const float*)d_in[7];
    const float* proj_b = (const float*)d_in[8];
    const int*   rel    = (const int*)d_in[9];
    float* out = (float*)d_out;

    unsigned short *xh,*xl,*mh,*ml,*oh,*ol,*qwh,*qwl,*kvwh,*kvwl,*pwh,*pwl;
    float *pq,*pkv;
    cudaGetSymbolAddress((void**)&xh,g_xh);     cudaGetSymbolAddress((void**)&xl,g_xl);
    cudaGetSymbolAddress((void**)&mh,g_mh);     cudaGetSymbolAddress((void**)&ml,g_ml);
    cudaGetSymbolAddress((void**)&oh,g_oh);     cudaGetSymbolAddress((void**)&ol,g_ol);
    cudaGetSymbolAddress((void**)&qwh,g_qwh);   cudaGetSymbolAddress((void**)&qwl,g_qwl);
    cudaGetSymbolAddress((void**)&kvwh,g_kvwh); cudaGetSymbolAddress((void**)&kvwl,g_kvwl);
    cudaGetSymbolAddress((void**)&pwh,g_pwh);   cudaGetSymbolAddress((void**)&pwl,g_pwl);
    cudaGetSymbolAddress((void**)&pq,g_q);      cudaGetSymbolAddress((void**)&pkv,g_kv);

    cudaFuncSetAttribute(gemm_mma, cudaFuncAttributeMaxDynamicSharedMemorySize, GEMM_SMEM);

    const float scale = 0.17677669529663687f;  // 32^-0.5
    long long n4x = (long long)BB*NTOK*CDIM/4;
    long long n4m = (long long)BB*TT*NTOK*CDIM/4;

    // Launch order keeps gemm_mma(KV) at slot #4 — the ncu window.
    split_kernel<<<(unsigned)((n4m+255)/256),256>>>(memory, mh, ml, n4m);        // #1
    split_kernel<<<(2*CDIM*CDIM/4+255)/256,256>>>(kv_w, kvwh, kvwl, 2*CDIM*CDIM/4); // #2
    split_kernel<<<(unsigned)((n4x+255)/256),256>>>(x, xh, xl, n4x);             // #3
    {   // #4 (PROFILED): KV = memory @ kv_w^T + kv_b   M=200704 N=1024
        dim3 g(2*CDIM/128, BB*TT*NTOK/128);
        gemm_mma<<<g, 256, GEMM_SMEM>>>(mh, ml, kvwh, kvwl, kv_b, pkv, 2*CDIM, 1.0f);
    }
    split_kernel<<<(CDIM*CDIM/4+255)/256,256>>>(q_w, qwh, qwl, CDIM*CDIM/4);     // #5
    {   // #6: Q = scale*(x @ q_w^T + q_b)              M=100352 N=512
        dim3 g(CDIM/128, BB*NTOK/128);
        gemm_mma<<<g, 256, GEMM_SMEM>>>(xh, xl, qwh, qwl, q_b, pq, CDIM, scale);
    }
    split_kernel<<<(CDIM*CDIM/4+255)/256,256>>>(proj_w, pwh, pwl, CDIM*CDIM/4);  // #7
    bias_gather_kernel<<<(NHEAD*NN2 + 255)/256, 256>>>(rpb, rel);                // #8
    attn_kernel<<<BB*TT*NHEAD, 128>>>();                                         // #9
    {   // #10: out = attn @ proj_w^T + proj_b          M=200704 N=512
        dim3 g(CDIM/128, BB*TT*NTOK/128);
        gemm_mma<<<g, 256, GEMM_SMEM>>>(oh, ol, pwh, pwl, proj_b, out, CDIM, 1.0f);
    }
    (void)in_sizes; (void)n_in; (void)out_size;
}

// round 14
// speedup vs baseline: 1.4876x; 1.3519x over previous
#include <cuda_runtime.h>
#include <cuda_bf16.h>
#include <cstdint>

#define BB 2048
#define TT 2
#define NTOK 49
#define NHEAD 16
#define HDIM 32
#define CDIM 512
#define NN2 (NTOK*NTOK)

// ---------------- scratch (device globals; no allocs allowed) ----------------
// GEMM operand arrays live in "chunked" layout: [rows/128][16][128*32 halves],
// each 8KB block contiguous + SW64-swizzled (so cp.async.bulk can load it raw).
__device__ __align__(16) unsigned short g_xh[(size_t)BB*NTOK*CDIM],    g_xl[(size_t)BB*NTOK*CDIM];
__device__ __align__(16) unsigned short g_mh[(size_t)BB*TT*NTOK*CDIM], g_ml[(size_t)BB*TT*NTOK*CDIM];
__device__ __align__(16) unsigned short g_oh[(size_t)BB*TT*NTOK*CDIM], g_ol[(size_t)BB*TT*NTOK*CDIM];
__device__ __align__(16) unsigned short g_qwh[CDIM*CDIM],    g_qwl[CDIM*CDIM];
__device__ __align__(16) unsigned short g_kvwh[2*CDIM*CDIM], g_kvwl[2*CDIM*CDIM];
__device__ __align__(16) unsigned short g_pwh[CDIM*CDIM],    g_pwl[CDIM*CDIM];
__device__ float g_q [(size_t)BB*NTOK*CDIM];
__device__ float g_kv[(size_t)BB*TT*NTOK*2*CDIM];
__device__ float g_bias[NHEAD*NN2];

// chunked-layout byte offset for element (row m, col k), K=512, swizzled
__device__ __forceinline__ size_t coff(int m, int k){
    unsigned inner = ((unsigned)(m & 127) << 6) + (((unsigned)k & 31) << 1);
    inner ^= (inner >> 3) & 0x30u;
    return ((size_t)(m >> 7) * 16 + (unsigned)(k >> 5)) * 8192 + inner;
}

// ---------------- PTX helpers (base-target only: sm_90-era features) ----------
__device__ __forceinline__ uint32_t smem_u32(const void* p){
    uint32_t a;
    asm("{ .reg .u64 t; cvta.to.shared.u64 t, %1; cvt.u32.u64 %0, t; }":"=r"(a):"l"(p));
    return a;
}
#define CP_BULK(dst, src, mbar) \
    asm volatile("cp.async.bulk.shared::cta.global.mbarrier::complete_tx::bytes [%0], [%1], %2, [%3];" \
        :: "r"((uint32_t)(dst)), "l"(src), "r"(8192u), "r"((uint32_t)(mbar)) : "memory")
#define MB_INIT(a,c) asm volatile("mbarrier.init.shared.b64 [%0], %1;"::"r"((uint32_t)(a)),"r"((uint32_t)(c)):"memory")
#define MB_EXPECT(a,tx) asm volatile("mbarrier.arrive.expect_tx.shared.b64 _, [%0], %1;"::"r"((uint32_t)(a)),"r"((uint32_t)(tx)):"memory")
#define MB_WAIT(a,p) do{ uint32_t _m=(uint32_t)(a),_p=(uint32_t)(p),_d; \
    asm volatile("{\n\t.reg .pred q;\n\tmbarrier.try_wait.parity.acquire.cta.shared::cta.b64 q, [%1], %2;\n\tselp.b32 %0,1,0,q;\n\t}":"=r"(_d):"r"(_m),"r"(_p):"memory"); \
    if(!_d){ asm volatile("{\n\t.reg .pred P;\n\tWL_%=:\n\tmbarrier.try_wait.parity.acquire.cta.shared::cta.b64 P, [%0], %1, 0x989680;\n\t@P bra.uni WD_%=;\n\tbra.uni WL_%=;\n\tWD_%=:\n\t}"::"r"(_m),"r"(_p):"memory"); } }while(0)
#define FENCE_ASY() asm volatile("fence.proxy.async.shared::cta;":::"memory")

__device__ __forceinline__ void ldsm4(uint32_t* r, uint32_t addr){
    asm volatile("ldmatrix.sync.aligned.m8n8.x4.shared.b16 {%0,%1,%2,%3}, [%4];"
        : "=r"(r[0]),"=r"(r[1]),"=r"(r[2]),"=r"(r[3]) : "r"(addr));
}
__device__ __forceinline__ void mma16816(float* d, const uint32_t* a, const uint32_t* b){
    asm volatile("mma.sync.aligned.m16n8k16.row.col.f32.bf16.bf16.f32 "
        "{%0,%1,%2,%3}, {%4,%5,%6,%7}, {%8,%9}, {%0,%1,%2,%3};"
        : "+f"(d[0]),"+f"(d[1]),"+f"(d[2]),"+f"(d[3])
        : "r"(a[0]),"r"(a[1]),"r"(a[2]),"r"(a[3]), "r"(b[0]),"r"(b[1]));
}

// ---------------- fp32 -> bf16 hi/lo split into chunked layout ----------------
// every source array has row length 512 fp32; i4 indexes float4s.
__global__ void split_kernel(const float* __restrict__ in,
                             unsigned short* __restrict__ hi,
                             unsigned short* __restrict__ lo, long long n4){
    long long i = (long long)blockIdx.x*256 + threadIdx.x;
    if (i >= n4) return;
    int m  = (int)(i >> 7);          // 128 float4 per row
    int k4 = (int)(i & 127);
    float4 v = reinterpret_cast<const float4*>(in)[i];
    float vs[4] = {v.x, v.y, v.z, v.w};
    unsigned short hb[4], lb[4];
#pragma unroll
    for (int c = 0; c < 4; c++){
        __nv_bfloat16 h = __float2bfloat16_rn(vs[c]);
        float r = vs[c] - __bfloat162float(h);
        hb[c] = __bfloat16_as_ushort(h);
        lb[c] = __bfloat16_as_ushort(__float2bfloat16_rn(r));
    }
    uint2 H, L;
    H.x = hb[0] | ((uint32_t)hb[1] << 16);  H.y = hb[2] | ((uint32_t)hb[3] << 16);
    L.x = lb[0] | ((uint32_t)lb[1] << 16);  L.y = lb[2] | ((uint32_t)lb[3] << 16);
    size_t off = coff(m, k4 << 2);   // 8B-aligned; swizzle preserves 8B units
    *reinterpret_cast<uint2*>((char*)hi + off) = H;
    *reinterpret_cast<uint2*>((char*)lo + off) = L;
}

// ---------------- bias gather ----------------
__global__ void bias_gather_kernel(const float* __restrict__ rpb,
                                   const int* __restrict__ rel){
    int g = blockIdx.x*256 + threadIdx.x;
    if (g >= NHEAD*NN2) return;
    int h = g / NN2, p = g - h*NN2;
    g_bias[g] = rpb[rel[p]*NHEAD + h];
}

// ---------------- warp-MMA GEMM, bulk-DMA loads ----------------
// 3-term compensated bf16 (K'=1536 = AhWh|AlWh|AhWl). Tile 128x128, BK=32,
// 48 chunks. Per chunk: TWO cp.async.bulk (8KB each) from one thread,
// mbarrier complete_tx; all threads wait parity. One __syncthreads per iter
// (WAR safety before refilling stage (t+3)&3). 4 stages = 64KB smem.
#define STB    16384u            // bytes per stage (A 8KB + W 8KB)
#define NSTAGE 4
#define GEMM_SMEM (NSTAGE*16384 + 64)
#define NCHUNK 48

__global__ __launch_bounds__(256, 2)
void gemm_mma(const unsigned short* __restrict__ Ah, const unsigned short* __restrict__ Al,
              const unsigned short* __restrict__ Wh, const unsigned short* __restrict__ Wl,
              const float* __restrict__ bias, float* __restrict__ C, int N, float alpha){
    extern __shared__ __align__(128) unsigned char dyn[];
    const uint32_t base = smem_u32(dyn);
    const uint32_t mb0  = base + NSTAGE*16384;          // 4 mbarriers, 8B apart

    const int tid = threadIdx.x, lane = tid & 31, wid = tid >> 5;
    const int wm = wid & 1, wn = wid >> 1;              // 2 x 4 warp grid
    const int m0 = blockIdx.y * 128, n0 = blockIdx.x * 128;

    const char* AP[3] = {(const char*)Ah, (const char*)Al, (const char*)Ah};
    const char* WP[3] = {(const char*)Wh, (const char*)Wh, (const char*)Wl};

    if (tid == 0){
#pragma unroll
        for (int s = 0; s < NSTAGE; s++) MB_INIT(mb0 + s*8, 1);
        FENCE_ASY();
    }
    __syncthreads();

    auto issue_chunk = [&](int t, int s){               // thread 0 only
        const char* srcA = AP[t >> 4] + ((size_t)blockIdx.y*16 + (t & 15))*8192;
        const char* srcW = WP[t >> 4] + ((size_t)blockIdx.x*16 + (t & 15))*8192;
        uint32_t bar = mb0 + s*8;
        MB_EXPECT(bar, 16384u);
        CP_BULK(base + s*16384,        srcA, bar);
        CP_BULK(base + s*16384 + 8192, srcW, bar);
    };
    if (tid == 0){ issue_chunk(0,0); issue_chunk(1,1); issue_chunk(2,2); }

    // lane offsets within an 8KB block (64B rows, SW64 swizzle)
    uint32_t a_off[4], a_msk[4], b_off[2], b_msk[2];
#pragma unroll
    for (int mt = 0; mt < 4; mt++){
        int r = wm*64 + mt*16 + (lane & 15);
        a_off[mt] = (uint32_t)(r*64 + ((lane >> 4) & 1)*16);
        a_msk[mt] = (uint32_t)(((r >> 1) & 3) << 4);
    }
    {
        int g = lane >> 3;
#pragma unroll
        for (int q = 0; q < 2; q++){
            int r = wn*32 + (2*q + (g >> 1))*8 + (lane & 7);
            b_off[q] = (uint32_t)(r*64 + (g & 1)*16);
            b_msk[q] = (uint32_t)(((r >> 1) & 3) << 4);
        }
    }

    float acc[4][4][4];
#pragma unroll
    for (int i = 0; i < 4; i++)
#pragma unroll
        for (int j = 0; j < 4; j++)
#pragma unroll
            for (int k = 0; k < 4; k++) acc[i][j][k] = 0.f;

    for (int t = 0; t < NCHUNK; ++t){
        const int s = t & (NSTAGE - 1);
        const uint32_t ab = base + s*16384;
        const uint32_t wb = ab + 8192;
        MB_WAIT(mb0 + s*8, (t >> 2) & 1);

#pragma unroll
        for (int ks = 0; ks < 2; ks++){                  // 2 x k16 within BK=32
            uint32_t af[4][4], bf[2][4];
#pragma unroll
            for (int mt = 0; mt < 4; mt++)
                ldsm4(af[mt], ab + ((a_off[mt] + ks*32) ^ a_msk[mt]));
#pragma unroll
            for (int q = 0; q < 2; q++)
                ldsm4(bf[q],  wb + ((b_off[q] + ks*32) ^ b_msk[q]));
#pragma unroll
            for (int mt = 0; mt < 4; mt++){
                mma16816(acc[mt][0], af[mt], bf[0] + 0);
                mma16816(acc[mt][1], af[mt], bf[0] + 2);
                mma16816(acc[mt][2], af[mt], bf[1] + 0);
                mma16816(acc[mt][3], af[mt], bf[1] + 2);
            }
        }
        __syncthreads();                                 // all reads of stage (t+3)&3 done
        if (t + 3 < NCHUNK && tid == 0) issue_chunk(t + 3, (t + 3) & (NSTAGE - 1));
    }

    // epilogue
#pragma unroll
    for (int mt = 0; mt < 4; mt++){
#pragma unroll
        for (int nt = 0; nt < 4; nt++){
            int rg = m0 + wm*64 + mt*16 + (lane >> 2);
            int cg = n0 + wn*32 + nt*8 + 2*(lane & 3);
            float b0 = bias[cg], b1 = bias[cg + 1];
            float2 o0 = make_float2(alpha*(acc[mt][nt][0] + b0), alpha*(acc[mt][nt][1] + b1));
            float2 o1 = make_float2(alpha*(acc[mt][nt][2] + b0), alpha*(acc[mt][nt][3] + b1));
            *reinterpret_cast<float2*>(C + (size_t)rg*N + cg)       = o0;
            *reinterpret_cast<float2*>(C + (size_t)(rg + 8)*N + cg) = o1;
        }
    }
}

// ---------------- attention: 4x4 register-blocked, chunked bf16-split out ----
#define QP 36
#define SP 56

__global__ __launch_bounds__(128)
void attn_kernel(){
    const int bh = blockIdx.x;
    const int h  = bh & (NHEAD-1);
    const int bt = bh >> 4;
    const int b  = bt >> 1;
    __shared__ __align__(16) float sq[52*QP], sk[52*QP], sv[52*QP], sS[52*SP];
    const int tid = threadIdx.x;

    for (int p = tid; p < 52*HDIM; p += 128){
        int i = p >> 5, d = p & 31;
        float qv = 0.f, kv = 0.f, vv = 0.f;
        if (i < NTOK){
            qv = g_q[(size_t)(b*NTOK+i)*CDIM + h*HDIM + d];
            const float* kvr = g_kv + (size_t)(bt*NTOK+i)*(2*CDIM) + h*HDIM + d;
            kv = kvr[0];
            vv = kvr[CDIM];
        }
        sq[i*QP+d] = qv;
        sk[i*QP+d] = kv;
        sv[i*QP+d] = vv;
    }
    __syncthreads();

    const float* biasH = g_bias + h*NN2;
    for (int p = tid; p < 169; p += 128){
        int ti = p / 13, tj = p - ti*13;
        int i0 = ti*4, j0 = tj*4;
        float a[4][4] = {};
#pragma unroll
        for (int dd = 0; dd < 8; dd++){
            float4 qa[4], kb[4];
#pragma unroll
            for (int r = 0; r < 4; r++) qa[r] = *reinterpret_cast<const float4*>(&sq[(i0+r)*QP + dd*4]);
#pragma unroll
            for (int c = 0; c < 4; c++) kb[c] = *reinterpret_cast<const float4*>(&sk[(j0+c)*QP + dd*4]);
#pragma unroll
            for (int r = 0; r < 4; r++)
#pragma unroll
                for (int c = 0; c < 4; c++)
                    a[r][c] += qa[r].x*kb[c].x + qa[r].y*kb[c].y + qa[r].z*kb[c].z + qa[r].w*kb[c].w;
        }
#pragma unroll
        for (int r = 0; r < 4; r++)
#pragma unroll
            for (int c = 0; c < 4; c++){
                int i = i0 + r, j = j0 + c;
                float bv = (i < NTOK && j < NTOK) ? biasH[i*NTOK + j] : 0.f;
                sS[i*SP + j] = a[r][c] + bv;
            }
    }
    __syncthreads();

    const int warp = tid >> 5, lane = tid & 31;
    for (int i = warp; i < NTOK; i += 4){
        float* row = sS + i*SP;
        float x0 = row[lane];
        bool  v1 = (lane + 32) < NTOK;
        float x1 = v1 ? row[lane+32] : -3.402823466e38f;
        float m = fmaxf(x0, x1);
#pragma unroll
        for (int o = 16; o > 0; o >>= 1) m = fmaxf(m, __shfl_xor_sync(0xffffffffu, m, o));
        float e0 = __expf(x0 - m);
        float e1 = v1 ? __expf(x1 - m) : 0.f;
        float s = e0 + e1;
#pragma unroll
        for (int o = 16; o > 0; o >>= 1) s += __shfl_xor_sync(0xffffffffu, s, o);
        float inv = 1.0f / s;
        row[lane] = e0*inv;
        if (v1) row[lane+32] = e1*inv;
    }
    __syncthreads();

    for (int p = tid; p < 104; p += 128){
        int ti = p >> 3, td = p & 7;
        int i0 = ti*4, d0 = td*4;
        float a[4][4] = {};
        for (int m = 0; m < NTOK; m++){
            float4 vv = *reinterpret_cast<const float4*>(&sv[m*QP + d0]);
            float s0 = sS[(i0+0)*SP + m];
            float s1 = sS[(i0+1)*SP + m];
            float s2 = sS[(i0+2)*SP + m];
            float s3 = sS[(i0+3)*SP + m];
            a[0][0] += s0*vv.x; a[0][1] += s0*vv.y; a[0][2] += s0*vv.z; a[0][3] += s0*vv.w;
            a[1][0] += s1*vv.x; a[1][1] += s1*vv.y; a[1][2] += s1*vv.z; a[1][3] += s1*vv.w;
            a[2][0] += s2*vv.x; a[2][1] += s2*vv.y; a[2][2] += s2*vv.z; a[2][3] += s2*vv.w;
            a[3][0] += s3*vv.x; a[3][1] += s3*vv.y; a[3][2] += s3*vv.z; a[3][3] += s3*vv.w;
        }
#pragma unroll
        for (int r = 0; r < 4; r++){
            int i = i0 + r;
            if (i >= NTOK) break;
            int m = bt*NTOK + i;
            int k = h*HDIM + d0;
            unsigned short hb[4], lb[4];
#pragma unroll
            for (int c = 0; c < 4; c++){
                __nv_bfloat16 hh = __float2bfloat16_rn(a[r][c]);
                hb[c] = __bfloat16_as_ushort(hh);
                lb[c] = __bfloat16_as_ushort(__float2bfloat16_rn(a[r][c] - __bfloat162float(hh)));
            }
            uint2 H, L;
            H.x = hb[0] | ((uint32_t)hb[1] << 16);  H.y = hb[2] | ((uint32_t)hb[3] << 16);
            L.x = lb[0] | ((uint32_t)lb[1] << 16);  L.y = lb[2] | ((uint32_t)lb[3] << 16);
            size_t off = coff(m, k);
            *reinterpret_cast<uint2*>((char*)g_oh + off) = H;
            *reinterpret_cast<uint2*>((char*)g_ol + off) = L;
        }
    }
}

// ---------------- launch ----------------
extern "C" void kernel_launch(void* const* d_in, const int* in_sizes, int n_in,
                              void* d_out, int out_size){
    const float* x      = (const float*)d_in[0];
    const float* memory = (const float*)d_in[1];
    const float* rpb    = (const float*)d_in[2];
    const float* q_w    = (const float*)d_in[3];
    const float* q_b    = (const float*)d_in[4];
    const float* kv_w   = (const float*)d_in[5];
    const float* kv_b   = (const float*)d_in[6];
    const float* proj_w = (const float*)d_in[7];
    const float* proj_b = (const float*)d_in[8];
    const int*   rel    = (const int*)d_in[9];
    float* out = (float*)d_out;

    unsigned short *xh,*xl,*mh,*ml,*oh,*ol,*qwh,*qwl,*kvwh,*kvwl,*pwh,*pwl;
    float *pq,*pkv;
    cudaGetSymbolAddress((void**)&xh,g_xh);     cudaGetSymbolAddress((void**)&xl,g_xl);
    cudaGetSymbolAddress((void**)&mh,g_mh);     cudaGetSymbolAddress((void**)&ml,g_ml);
    cudaGetSymbolAddress((void**)&oh,g_oh);     cudaGetSymbolAddress((void**)&ol,g_ol);
    cudaGetSymbolAddress((void**)&qwh,g_qwh);   cudaGetSymbolAddress((void**)&qwl,g_qwl);
    cudaGetSymbolAddress((void**)&kvwh,g_kvwh); cudaGetSymbolAddress((void**)&kvwl,g_kvwl);
    cudaGetSymbolAddress((void**)&pwh,g_pwh);   cudaGetSymbolAddress((void**)&pwl,g_pwl);
    cudaGetSymbolAddress((void**)&pq,g_q);      cudaGetSymbolAddress((void**)&pkv,g_kv);

    cudaFuncSetAttribute(gemm_mma, cudaFuncAttributeMaxDynamicSharedMemorySize, GEMM_SMEM);

    const float scale = 0.17677669529663687f;  // 32^-0.5
    long long n4x = (long long)BB*NTOK*CDIM/4;
    long long n4m = (long long)BB*TT*NTOK*CDIM/4;

    // Launch order keeps gemm_mma(KV) at slot #4 — the ncu window.
    split_kernel<<<(unsigned)((n4m+255)/256),256>>>(memory, mh, ml, n4m);        // #1
    split_kernel<<<(2*CDIM*CDIM/4+255)/256,256>>>(kv_w, kvwh, kvwl, 2*CDIM*CDIM/4); // #2
    split_kernel<<<(unsigned)((n4x+255)/256),256>>>(x, xh, xl, n4x);             // #3
    {   // #4 (PROFILED): KV = memory @ kv_w^T + kv_b   M=200704 N=1024
        dim3 g(2*CDIM/128, BB*TT*NTOK/128);
        gemm_mma<<<g, 256, GEMM_SMEM>>>(mh, ml, kvwh, kvwl, kv_b, pkv, 2*CDIM, 1.0f);
    }
    split_kernel<<<(CDIM*CDIM/4+255)/256,256>>>(q_w, qwh, qwl, CDIM*CDIM/4);     // #5
    {   // #6: Q = scale*(x @ q_w^T + q_b)              M=100352 N=512
        dim3 g(CDIM/128, BB*NTOK/128);
        gemm_mma<<<g, 256, GEMM_SMEM>>>(xh, xl, qwh, qwl, q_b, pq, CDIM, scale);
    }
    split_kernel<<<(CDIM*CDIM/4+255)/256,256>>>(proj_w, pwh, pwl, CDIM*CDIM/4);  // #7
    bias_gather_kernel<<<(NHEAD*NN2 + 255)/256, 256>>>(rpb, rel);                // #8
    attn_kernel<<<BB*TT*NHEAD, 128>>>();                                         // #9
    {   // #10: out = attn @ proj_w^T + proj_b          M=200704 N=512
        dim3 g(CDIM/128, BB*TT*NTOK/128);
        gemm_mma<<<g, 256, GEMM_SMEM>>>(oh, ol, pwh, pwl, proj_b, out, CDIM, 1.0f);
    }
    (void)in_sizes; (void)n_in; (void)out_size;
}

// round 15
// speedup vs baseline: 1.7727x; 1.1916x over previous
#include <cuda_runtime.h>
#include <cuda_fp16.h>
#include <cstdint>

#define BB 2048
#define TT 2
#define NTOK 49
#define NHEAD 16
#define HDIM 32
#define CDIM 512
#define NN2 (NTOK*NTOK)

// ---------------- scratch (device globals; no allocs allowed) ----------------
// GEMM operand arrays live in "chunked" layout: [rows/128][16][128*32 halves],
// each 8KB block contiguous + SW64-swizzled (so cp.async.bulk can load it raw).
__device__ __align__(16) unsigned short g_xh[(size_t)BB*NTOK*CDIM],    g_xl[(size_t)BB*NTOK*CDIM];
__device__ __align__(16) unsigned short g_mh[(size_t)BB*TT*NTOK*CDIM], g_ml[(size_t)BB*TT*NTOK*CDIM];
__device__ __align__(16) unsigned short g_oh[(size_t)BB*TT*NTOK*CDIM], g_ol[(size_t)BB*TT*NTOK*CDIM];
__device__ __align__(16) unsigned short g_qwh[CDIM*CDIM],    g_qwl[CDIM*CDIM];
__device__ __align__(16) unsigned short g_kvwh[2*CDIM*CDIM], g_kvwl[2*CDIM*CDIM];
__device__ __align__(16) unsigned short g_pwh[CDIM*CDIM],    g_pwl[CDIM*CDIM];
__device__ float g_q [(size_t)BB*NTOK*CDIM];
__device__ float g_kv[(size_t)BB*TT*NTOK*2*CDIM];
__device__ float g_bias[NHEAD*NN2];

// chunked-layout byte offset for element (row m, col k), K=512, swizzled
__device__ __forceinline__ size_t coff(int m, int k){
    unsigned inner = ((unsigned)(m & 127) << 6) + (((unsigned)k & 31) << 1);
    inner ^= (inner >> 3) & 0x30u;
    return ((size_t)(m >> 7) * 16 + (unsigned)(k >> 5)) * 8192 + inner;
}

// ---------------- PTX helpers (base-target only: sm_90-era features) ----------
__device__ __forceinline__ uint32_t smem_u32(const void* p){
    uint32_t a;
    asm("{ .reg .u64 t; cvta.to.shared.u64 t, %1; cvt.u32.u64 %0, t; }":"=r"(a):"l"(p));
    return a;
}
#define CP_BULK(dst, src, mbar) \
    asm volatile("cp.async.bulk.shared::cta.global.mbarrier::complete_tx::bytes [%0], [%1], %2, [%3];" \
        :: "r"((uint32_t)(dst)), "l"(src), "r"(8192u), "r"((uint32_t)(mbar)) : "memory")
#define MB_INIT(a,c) asm volatile("mbarrier.init.shared.b64 [%0], %1;"::"r"((uint32_t)(a)),"r"((uint32_t)(c)):"memory")
#define MB_EXPECT(a,tx) asm volatile("mbarrier.arrive.expect_tx.shared.b64 _, [%0], %1;"::"r"((uint32_t)(a)),"r"((uint32_t)(tx)):"memory")
#define MB_WAIT(a,p) do{ uint32_t _m=(uint32_t)(a),_p=(uint32_t)(p),_d; \
    asm volatile("{\n\t.reg .pred q;\n\tmbarrier.try_wait.parity.acquire.cta.shared::cta.b64 q, [%1], %2;\n\tselp.b32 %0,1,0,q;\n\t}":"=r"(_d):"r"(_m),"r"(_p):"memory"); \
    if(!_d){ asm volatile("{\n\t.reg .pred P;\n\tWL_%=:\n\tmbarrier.try_wait.parity.acquire.cta.shared::cta.b64 P, [%0], %1, 0x989680;\n\t@P bra.uni WD_%=;\n\tbra.uni WL_%=;\n\tWD_%=:\n\t}"::"r"(_m),"r"(_p):"memory"); } }while(0)
#define FENCE_ASY() asm volatile("fence.proxy.async.shared::cta;":::"memory")

__device__ __forceinline__ void ldsm4(uint32_t* r, uint32_t addr){
    asm volatile("ldmatrix.sync.aligned.m8n8.x4.shared.b16 {%0,%1,%2,%3}, [%4];"
        : "=r"(r[0]),"=r"(r[1]),"=r"(r[2]),"=r"(r[3]) : "r"(addr));
}
__device__ __forceinline__ void mma16816(float* d, const uint32_t* a, const uint32_t* b){
    asm volatile("mma.sync.aligned.m16n8k16.row.col.f32.f16.f16.f32 "
        "{%0,%1,%2,%3}, {%4,%5,%6,%7}, {%8,%9}, {%0,%1,%2,%3};"
        : "+f"(d[0]),"+f"(d[1]),"+f"(d[2]),"+f"(d[3])
        : "r"(a[0]),"r"(a[1]),"r"(a[2]),"r"(a[3]), "r"(b[0]),"r"(b[1]));
}

// ---------------- fp32 -> fp16 hi/lo split into chunked layout ----------------
// fp16 10-bit mantissa: hi = rn(v), lo = rn(v - hi). A-side uses both terms
// (exact A reconstruction in the 2-term product); W-side uses hi only.
__global__ void split_kernel(const float* __restrict__ in,
                             unsigned short* __restrict__ hi,
                             unsigned short* __restrict__ lo, long long n4){
    long long i = (long long)blockIdx.x*256 + threadIdx.x;
    if (i >= n4) return;
    int m  = (int)(i >> 7);          // 128 float4 per row
    int k4 = (int)(i & 127);
    float4 v = reinterpret_cast<const float4*>(in)[i];
    float vs[4] = {v.x, v.y, v.z, v.w};
    unsigned short hb[4], lb[4];
#pragma unroll
    for (int c = 0; c < 4; c++){
        __half h = __float2half_rn(vs[c]);
        float r = vs[c] - __half2float(h);
        hb[c] = __half_as_ushort(h);
        lb[c] = __half_as_ushort(__float2half_rn(r));
    }
    uint2 H, L;
    H.x = hb[0] | ((uint32_t)hb[1] << 16);  H.y = hb[2] | ((uint32_t)hb[3] << 16);
    L.x = lb[0] | ((uint32_t)lb[1] << 16);  L.y = lb[2] | ((uint32_t)lb[3] << 16);
    size_t off = coff(m, k4 << 2);   // 8B-aligned; swizzle preserves 8B units
    *reinterpret_cast<uint2*>((char*)hi + off) = H;
    *reinterpret_cast<uint2*>((char*)lo + off) = L;
}

// ---------------- bias gather ----------------
__global__ void bias_gather_kernel(const float* __restrict__ rpb,
                                   const int* __restrict__ rel){
    int g = blockIdx.x*256 + threadIdx.x;
    if (g >= NHEAD*NN2) return;
    int h = g / NN2, p = g - h*NN2;
    g_bias[g] = rpb[rel[p]*NHEAD + h];
}

// ---------------- warp-MMA GEMM, bulk-DMA loads ----------------
// 2-term compensated fp16 (K'=1024 = AhWh|AlWh; W low term not needed since
// (Ah+Al)Wh = A*Wh, error = A*(W-Wh) ~ 2^-11). Tile 128x128, BK=32, 32 chunks.
// Per chunk: TWO cp.async.bulk (8KB) from one thread, mbarrier complete_tx.
// One __syncthreads per iter (WAR before refilling stage (t+3)&3). 4 stages.
#define NSTAGE 4
#define GEMM_SMEM (NSTAGE*16384 + 64)
#define NCHUNK 32

__global__ __launch_bounds__(256, 2)
void gemm_mma(const unsigned short* __restrict__ Ah, const unsigned short* __restrict__ Al,
              const unsigned short* __restrict__ Wh,
              const float* __restrict__ bias, float* __restrict__ C, int N, float alpha){
    extern __shared__ __align__(128) unsigned char dyn[];
    const uint32_t base = smem_u32(dyn);
    const uint32_t mb0  = base + NSTAGE*16384;          // 4 mbarriers, 8B apart

    const int tid = threadIdx.x, lane = tid & 31, wid = tid >> 5;
    const int wm = wid & 1, wn = wid >> 1;              // 2 x 4 warp grid
    const int m0 = blockIdx.y * 128, n0 = blockIdx.x * 128;

    const char* AP[2] = {(const char*)Ah, (const char*)Al};

    if (tid == 0){
#pragma unroll
        for (int s = 0; s < NSTAGE; s++) MB_INIT(mb0 + s*8, 1);
        FENCE_ASY();
    }
    __syncthreads();

    auto issue_chunk = [&](int t, int s){               // thread 0 only
        const char* srcA = AP[t >> 4] + ((size_t)blockIdx.y*16 + (t & 15))*8192;
        const char* srcW = (const char*)Wh + ((size_t)blockIdx.x*16 + (t & 15))*8192;
        uint32_t bar = mb0 + s*8;
        MB_EXPECT(bar, 16384u);
        CP_BULK(base + s*16384,        srcA, bar);
        CP_BULK(base + s*16384 + 8192, srcW, bar);
    };
    if (tid == 0){ issue_chunk(0,0); issue_chunk(1,1); issue_chunk(2,2); }

    // lane offsets within an 8KB block (64B rows, SW64 swizzle)
    uint32_t a_off[4], a_msk[4], b_off[2], b_msk[2];
#pragma unroll
    for (int mt = 0; mt < 4; mt++){
        int r = wm*64 + mt*16 + (lane & 15);
        a_off[mt] = (uint32_t)(r*64 + ((lane >> 4) & 1)*16);
        a_msk[mt] = (uint32_t)(((r >> 1) & 3) << 4);
    }
    {
        int g = lane >> 3;
#pragma unroll
        for (int q = 0; q < 2; q++){
            int r = wn*32 + (2*q + (g >> 1))*8 + (lane & 7);
            b_off[q] = (uint32_t)(r*64 + (g & 1)*16);
            b_msk[q] = (uint32_t)(((r >> 1) & 3) << 4);
        }
    }

    float acc[4][4][4];
#pragma unroll
    for (int i = 0; i < 4; i++)
#pragma unroll
        for (int j = 0; j < 4; j++)
#pragma unroll
            for (int k = 0; k < 4; k++) acc[i][j][k] = 0.f;

    for (int t = 0; t < NCHUNK; ++t){
        const int s = t & (NSTAGE - 1);
        const uint32_t ab = base + s*16384;
        const uint32_t wb = ab + 8192;
        MB_WAIT(mb0 + s*8, (t >> 2) & 1);

#pragma unroll
        for (int ks = 0; ks < 2; ks++){                  // 2 x k16 within BK=32
            uint32_t af[4][4], bf[2][4];
#pragma unroll
            for (int mt = 0; mt < 4; mt++)
                ldsm4(af[mt], ab + ((a_off[mt] + ks*32) ^ a_msk[mt]));
#pragma unroll
            for (int q = 0; q < 2; q++)
                ldsm4(bf[q],  wb + ((b_off[q] + ks*32) ^ b_msk[q]));
#pragma unroll
            for (int mt = 0; mt < 4; mt++){
                mma16816(acc[mt][0], af[mt], bf[0] + 0);
                mma16816(acc[mt][1], af[mt], bf[0] + 2);
                mma16816(acc[mt][2], af[mt], bf[1] + 0);
                mma16816(acc[mt][3], af[mt], bf[1] + 2);
            }
        }
        __syncthreads();                                 // all reads of stage (t+3)&3 done
        if (t + 3 < NCHUNK && tid == 0) issue_chunk(t + 3, (t + 3) & (NSTAGE - 1));
    }

    // epilogue
#pragma unroll
    for (int mt = 0; mt < 4; mt++){
#pragma unroll
        for (int nt = 0; nt < 4; nt++){
            int rg = m0 + wm*64 + mt*16 + (lane >> 2);
            int cg = n0 + wn*32 + nt*8 + 2*(lane & 3);
            float b0 = bias[cg], b1 = bias[cg + 1];
            float2 o0 = make_float2(alpha*(acc[mt][nt][0] + b0), alpha*(acc[mt][nt][1] + b1));
            float2 o1 = make_float2(alpha*(acc[mt][nt][2] + b0), alpha*(acc[mt][nt][3] + b1));
            *reinterpret_cast<float2*>(C + (size_t)rg*N + cg)       = o0;
            *reinterpret_cast<float2*>(C + (size_t)(rg + 8)*N + cg) = o1;
        }
    }
}

// ---------------- attention: 4x4 register-blocked, chunked fp16-split out ----
#define QP 36
#define SP 56

__global__ __launch_bounds__(128)
void attn_kernel(){
    const int bh = blockIdx.x;
    const int h  = bh & (NHEAD-1);
    const int bt = bh >> 4;
    const int b  = bt >> 1;
    __shared__ __align__(16) float sq[52*QP], sk[52*QP], sv[52*QP], sS[52*SP];
    const int tid = threadIdx.x;

    for (int p = tid; p < 52*HDIM; p += 128){
        int i = p >> 5, d = p & 31;
        float qv = 0.f, kv = 0.f, vv = 0.f;
        if (i < NTOK){
            qv = g_q[(size_t)(b*NTOK+i)*CDIM + h*HDIM + d];
            const float* kvr = g_kv + (size_t)(bt*NTOK+i)*(2*CDIM) + h*HDIM + d;
            kv = kvr[0];
            vv = kvr[CDIM];
        }
        sq[i*QP+d] = qv;
        sk[i*QP+d] = kv;
        sv[i*QP+d] = vv;
    }
    __syncthreads();

    const float* biasH = g_bias + h*NN2;
    for (int p = tid; p < 169; p += 128){
        int ti = p / 13, tj = p - ti*13;
        int i0 = ti*4, j0 = tj*4;
        float a[4][4] = {};
#pragma unroll
        for (int dd = 0; dd < 8; dd++){
            float4 qa[4], kb[4];
#pragma unroll
            for (int r = 0; r < 4; r++) qa[r] = *reinterpret_cast<const float4*>(&sq[(i0+r)*QP + dd*4]);
#pragma unroll
            for (int c = 0; c < 4; c++) kb[c] = *reinterpret_cast<const float4*>(&sk[(j0+c)*QP + dd*4]);
#pragma unroll
            for (int r = 0; r < 4; r++)
#pragma unroll
                for (int c = 0; c < 4; c++)
                    a[r][c] += qa[r].x*kb[c].x + qa[r].y*kb[c].y + qa[r].z*kb[c].z + qa[r].w*kb[c].w;
        }
#pragma unroll
        for (int r = 0; r < 4; r++)
#pragma unroll
            for (int c = 0; c < 4; c++){
                int i = i0 + r, j = j0 + c;
                float bv = (i < NTOK && j < NTOK) ? biasH[i*NTOK + j] : 0.f;
                sS[i*SP + j] = a[r][c] + bv;
            }
    }
    __syncthreads();

    const int warp = tid >> 5, lane = tid & 31;
    for (int i = warp; i < NTOK; i += 4){
        float* row = sS + i*SP;
        float x0 = row[lane];
        bool  v1 = (lane + 32) < NTOK;
        float x1 = v1 ? row[lane+32] : -3.402823466e38f;
        float m = fmaxf(x0, x1);
#pragma unroll
        for (int o = 16; o > 0; o >>= 1) m = fmaxf(m, __shfl_xor_sync(0xffffffffu, m, o));
        float e0 = __expf(x0 - m);
        float e1 = v1 ? __expf(x1 - m) : 0.f;
        float s = e0 + e1;
#pragma unroll
        for (int o = 16; o > 0; o >>= 1) s += __shfl_xor_sync(0xffffffffu, s, o);
        float inv = 1.0f / s;
        row[lane] = e0*inv;
        if (v1) row[lane+32] = e1*inv;
    }
    __syncthreads();

    for (int p = tid; p < 104; p += 128){
        int ti = p >> 3, td = p & 7;
        int i0 = ti*4, d0 = td*4;
        float a[4][4] = {};
        for (int m = 0; m < NTOK; m++){
            float4 vv = *reinterpret_cast<const float4*>(&sv[m*QP + d0]);
            float s0 = sS[(i0+0)*SP + m];
            float s1 = sS[(i0+1)*SP + m];
            float s2 = sS[(i0+2)*SP + m];
            float s3 = sS[(i0+3)*SP + m];
            a[0][0] += s0*vv.x; a[0][1] += s0*vv.y; a[0][2] += s0*vv.z; a[0][3] += s0*vv.w;
            a[1][0] += s1*vv.x; a[1][1] += s1*vv.y; a[1][2] += s1*vv.z; a[1][3] += s1*vv.w;
            a[2][0] += s2*vv.x; a[2][1] += s2*vv.y; a[2][2] += s2*vv.z; a[2][3] += s2*vv.w;
            a[3][0] += s3*vv.x; a[3][1] += s3*vv.y; a[3][2] += s3*vv.z; a[3][3] += s3*vv.w;
        }
#pragma unroll
        for (int r = 0; r < 4; r++){
            int i = i0 + r;
            if (i >= NTOK) break;
            int m = bt*NTOK + i;
            int k = h*HDIM + d0;
            unsigned short hb[4], lb[4];
#pragma unroll
            for (int c = 0; c < 4; c++){
                __half hh = __float2half_rn(a[r][c]);
                hb[c] = __half_as_ushort(hh);
                lb[c] = __half_as_ushort(__float2half_rn(a[r][c] - __half2float(hh)));
            }
            uint2 H, L;
            H.x = hb[0] | ((uint32_t)hb[1] << 16);  H.y = hb[2] | ((uint32_t)hb[3] << 16);
            L.x = lb[0] | ((uint32_t)lb[1] << 16);  L.y = lb[2] | ((uint32_t)lb[3] << 16);
            size_t off = coff(m, k);
            *reinterpret_cast<uint2*>((char*)g_oh + off) = H;
            *reinterpret_cast<uint2*>((char*)g_ol + off) = L;
        }
    }
}

// ---------------- launch ----------------
extern "C" void kernel_launch(void* const* d_in, const int* in_sizes, int n_in,
                              void* d_out, int out_size){
    const float* x      = (const float*)d_in[0];
    const float* memory = (const float*)d_in[1];
    const float* rpb    = (const float*)d_in[2];
    const float* q_w    = (const float*)d_in[3];
    const float* q_b    = (const float*)d_in[4];
    const float* kv_w   = (const float*)d_in[5];
    const float* kv_b   = (const float*)d_in[6];
    const float* proj_w = (const float*)d_in[7];
    const float* proj_b = (const float*)d_in[8];
    const int*   rel    = (const int*)d_in[9];
    float* out = (float*)d_out;

    unsigned short *xh,*xl,*mh,*ml,*oh,*ol,*qwh,*qwl,*kvwh,*kvwl,*pwh,*pwl;
    float *pq,*pkv;
    cudaGetSymbolAddress((void**)&xh,g_xh);     cudaGetSymbolAddress((void**)&xl,g_xl);
    cudaGetSymbolAddress((void**)&mh,g_mh);     cudaGetSymbolAddress((void**)&ml,g_ml);
    cudaGetSymbolAddress((void**)&oh,g_oh);     cudaGetSymbolAddress((void**)&ol,g_ol);
    cudaGetSymbolAddress((void**)&qwh,g_qwh);   cudaGetSymbolAddress((void**)&qwl,g_qwl);
    cudaGetSymbolAddress((void**)&kvwh,g_kvwh); cudaGetSymbolAddress((void**)&kvwl,g_kvwl);
    cudaGetSymbolAddress((void**)&pwh,g_pwh);   cudaGetSymbolAddress((void**)&pwl,g_pwl);
    cudaGetSymbolAddress((void**)&pq,g_q);      cudaGetSymbolAddress((void**)&pkv,g_kv);

    cudaFuncSetAttribute(gemm_mma, cudaFuncAttributeMaxDynamicSharedMemorySize, GEMM_SMEM);

    const float scale = 0.17677669529663687f;  // 32^-0.5
    long long n4x = (long long)BB*NTOK*CDIM/4;
    long long n4m = (long long)BB*TT*NTOK*CDIM/4;

    // Launch order keeps gemm_mma(KV) at slot #4 — the ncu window.
    split_kernel<<<(unsigned)((n4m+255)/256),256>>>(memory, mh, ml, n4m);        // #1
    split_kernel<<<(2*CDIM*CDIM/4+255)/256,256>>>(kv_w, kvwh, kvwl, 2*CDIM*CDIM/4); // #2
    split_kernel<<<(unsigned)((n4x+255)/256),256>>>(x, xh, xl, n4x);             // #3
    {   // #4 (PROFILED): KV = memory @ kv_w^T + kv_b   M=200704 N=1024
        dim3 g(2*CDIM/128, BB*TT*NTOK/128);
        gemm_mma<<<g, 256, GEMM_SMEM>>>(mh, ml, kvwh, kv_b, pkv, 2*CDIM, 1.0f);
    }
    split_kernel<<<(CDIM*CDIM/4+255)/256,256>>>(q_w, qwh, qwl, CDIM*CDIM/4);     // #5
    {   // #6: Q = scale*(x @ q_w^T + q_b)              M=100352 N=512
        dim3 g(CDIM/128, BB*NTOK/128);
        gemm_mma<<<g, 256, GEMM_SMEM>>>(xh, xl, qwh, q_b, pq, CDIM, scale);
    }
    split_kernel<<<(CDIM*CDIM/4+255)/256,256>>>(proj_w, pwh, pwl, CDIM*CDIM/4);  // #7
    bias_gather_kernel<<<(NHEAD*NN2 + 255)/256, 256>>>(rpb, rel);                // #8
    attn_kernel<<<BB*TT*NHEAD, 128>>>();                                         // #9
    {   // #10: out = attn @ proj_w^T + proj_b          M=200704 N=512
        dim3 g(CDIM/128, BB*TT*NTOK/128);
        gemm_mma<<<g, 256, GEMM_SMEM>>>(oh, ol, pwh, proj_b, out, CDIM, 1.0f);
    }
    (void)in_sizes; (void)n_in; (void)out_size;
}